// round 1
// baseline (speedup 1.0000x reference)
#include <cuda_runtime.h>
#include <math.h>

#define BATCHN 2
#define SEQL   4096
#define DMODEL 1024
#define NH     16
#define HD     64
#define CHUNKL 64
#define NCH    64          // SEQ/CHUNK
#define CONVD  3072
#define DINP   3088
#define BHN    (BATCHN*NH) // 32
#define BSN    (BATCHN*SEQL)

// ---------------- scratch (static device globals; no allocation) -------------
__device__ float g_xw[(size_t)BSN*DINP];          // in_proj output [8192,3088]
__device__ float g_Cm[(size_t)BHN*SEQL*HD];       // Cm  [bh][s][n]
__device__ float g_Bm[(size_t)BHN*SEQL*HD];       // Bm  [bh][s][n]
__device__ float g_Xv[(size_t)BHN*SEQL*HD];       // xv  [bh][s][p]
__device__ float g_Av[(size_t)BHN*SEQL];          // A   [bh][s]
__device__ float g_cumA[(size_t)BHN*SEQL];        // within-chunk cumsum
__device__ float g_states[(size_t)BHN*NCH*HD*HD]; // per-chunk end states [bh][c][p][n]
__device__ float g_nstates[(size_t)BHN*NCH*HD*HD];// entering states
__device__ float g_Atot[BHN*NCH];
__device__ float g_ndec[BHN*NCH];
__device__ float g_nnew[BHN*NCH];
__device__ float g_Ydiag[(size_t)BHN*SEQL*HD];    // [bh][s][p]
__device__ float g_ndiag[(size_t)BHN*SEQL];
__device__ float g_Y[(size_t)BSN*DMODEL];         // normalized SSD output [b*s][1024]

// ---------------- SGEMM NT: C[m,n] = sum_k A[m,k]*B[n,k] ---------------------
__global__ __launch_bounds__(256, 2) void sgemm_nt_k(
    const float* __restrict__ A, const float* __restrict__ B,
    float* __restrict__ C, int M, int N, int K)
{
    __shared__ float As[16][128];
    __shared__ float Bs[16][128];
    const int bm = blockIdx.y * 128;
    const int bn = blockIdx.x * 128;
    const int tid = threadIdx.x;
    const int tx = tid & 15;   // along N
    const int ty = tid >> 4;   // along M
    float acc[8][8];
#pragma unroll
    for (int i = 0; i < 8; i++)
#pragma unroll
        for (int j = 0; j < 8; j++) acc[i][j] = 0.f;

    for (int k0 = 0; k0 < K; k0 += 16) {
#pragma unroll
        for (int r = 0; r < 2; r++) {
            int idx = tid + r * 256;       // 0..511
            int row = idx >> 2;            // 0..127
            int c4  = (idx & 3) << 2;      // 0,4,8,12
            float4 va = *(const float4*)(A + (size_t)(bm + row) * K + k0 + c4);
            As[c4 + 0][row] = va.x; As[c4 + 1][row] = va.y;
            As[c4 + 2][row] = va.z; As[c4 + 3][row] = va.w;
            float4 vb = make_float4(0.f, 0.f, 0.f, 0.f);
            if (bn + row < N)
                vb = *(const float4*)(B + (size_t)(bn + row) * K + k0 + c4);
            Bs[c4 + 0][row] = vb.x; Bs[c4 + 1][row] = vb.y;
            Bs[c4 + 2][row] = vb.z; Bs[c4 + 3][row] = vb.w;
        }
        __syncthreads();
#pragma unroll
        for (int kk = 0; kk < 16; kk++) {
            float a[8], b[8];
            *(float4*)&a[0] = *(const float4*)&As[kk][ty * 8];
            *(float4*)&a[4] = *(const float4*)&As[kk][ty * 8 + 4];
            *(float4*)&b[0] = *(const float4*)&Bs[kk][tx * 8];
            *(float4*)&b[4] = *(const float4*)&Bs[kk][tx * 8 + 4];
#pragma unroll
            for (int i = 0; i < 8; i++)
#pragma unroll
                for (int j = 0; j < 8; j++) acc[i][j] = fmaf(a[i], b[j], acc[i][j]);
        }
        __syncthreads();
    }
#pragma unroll
    for (int i = 0; i < 8; i++) {
        int row = bm + ty * 8 + i;
#pragma unroll
        for (int j = 0; j < 8; j += 4) {
            int col = bn + tx * 8 + j;
            if (col + 3 < N) {
                float4 v = make_float4(acc[i][j], acc[i][j + 1], acc[i][j + 2], acc[i][j + 3]);
                *(float4*)(C + (size_t)row * N + col) = v;
            } else {
#pragma unroll
                for (int jj = 0; jj < 4; jj++)
                    if (col + jj < N) C[(size_t)row * N + col + jj] = acc[i][j + jj];
            }
        }
    }
}

// --------------- depthwise causal conv (width 4) + split to SSD layout -------
__global__ void conv_split_k(const float* __restrict__ cw, const float* __restrict__ cb)
{
    int gi = blockIdx.x * blockDim.x + threadIdx.x;
    if (gi >= BSN * CONVD) return;
    int ch = gi % CONVD;
    int bs = gi / CONVD;
    int s  = bs % SEQL;
    int b  = bs / SEQL;
    float acc = cb[ch];
#pragma unroll
    for (int k = 0; k < 4; k++) {
        int ss = s - 3 + k;
        if (ss >= 0)
            acc = fmaf(g_xw[(size_t)(b * SEQL + ss) * DINP + ch], cw[ch * 4 + k], acc);
    }
    int sect = ch >> 10;
    int h = (ch & 1023) >> 6;
    int n = ch & 63;
    float* dst = (sect == 0) ? g_Cm : (sect == 1) ? g_Bm : g_Xv;
    dst[((size_t)(b * NH + h) * SEQL + s) * HD + n] = acc;
}

// --------------- A = w * w_base -----------------------------------------------
__global__ void a_scale_k(const float* __restrict__ w_base)
{
    int gi = blockIdx.x * blockDim.x + threadIdx.x;
    if (gi >= BSN * NH) return;
    int h  = gi % NH;
    int bs = gi / NH;
    int s  = bs % SEQL;
    int b  = bs / SEQL;
    g_Av[((size_t)(b * NH + h)) * SEQL + s] = g_xw[(size_t)bs * DINP + CONVD + h] * w_base[h];
}

// --------------- per-chunk tile kernel ----------------------------------------
// computes: cumA, within-chunk L, Y_diag, norm_diag, chunk end-state, norm_decay
__global__ __launch_bounds__(256) void chunk_k()
{
    extern __shared__ float sh[];
    float (*sC)[65]  = (float(*)[65])sh;
    float (*sB)[65]  = (float(*)[65])(sh + 64 * 65);
    float (*sX)[65]  = (float(*)[65])(sh + 2 * 64 * 65);
    float (*sGL)[65] = (float(*)[65])(sh + 3 * 64 * 65);
    __shared__ float scum[64];   // inclusive cumsum of A within chunk
    __shared__ float smn[64];    // prefix min of cumsum
    __shared__ float sds[64];    // decay_states (normalized)

    int bh = blockIdx.x >> 6;
    int c  = blockIdx.x & 63;
    int tid = threadIdx.x;
    size_t base = ((size_t)bh * SEQL + (size_t)c * CHUNKL) * HD;

    for (int i = tid; i < 64 * 64; i += 256) {
        int l = i >> 6, n = i & 63;
        sC[l][n] = g_Cm[base + i];
        sB[l][n] = g_Bm[base + i];
        sX[l][n] = g_Xv[base + i];
    }
    if (tid == 0) {
        float cum = 0.f, mpre = 1e30f;
        for (int l = 0; l < 64; l++) {
            cum += g_Av[(size_t)bh * SEQL + c * 64 + l];
            scum[l] = cum;
            mpre = fminf(mpre, cum);
            smn[l] = mpre;
            g_cumA[(size_t)bh * SEQL + c * 64 + l] = cum;
        }
        g_Atot[bh * NCH + c] = cum;
        float nd = 0.f;
        for (int l = 0; l < 64; l++) { sds[l] = expf(mpre - scum[l]); nd += sds[l]; }
        g_ndec[bh * NCH + c] = nd;
    }
    __syncthreads();

    int tj = (tid & 15) * 4;
    int ti = (tid >> 4) * 4;

    // GL[i][j] = (C_i . B_j) * exp(smn[i]-cum[j]) for j<=i else 0
    {
        float r[4][4];
#pragma unroll
        for (int a = 0; a < 4; a++)
#pragma unroll
            for (int b2 = 0; b2 < 4; b2++) r[a][b2] = 0.f;
        for (int n = 0; n < 64; n++) {
            float cv[4], bv[4];
#pragma unroll
            for (int a = 0; a < 4; a++) cv[a] = sC[ti + a][n];
#pragma unroll
            for (int b2 = 0; b2 < 4; b2++) bv[b2] = sB[tj + b2][n];
#pragma unroll
            for (int a = 0; a < 4; a++)
#pragma unroll
                for (int b2 = 0; b2 < 4; b2++) r[a][b2] = fmaf(cv[a], bv[b2], r[a][b2]);
        }
#pragma unroll
        for (int a = 0; a < 4; a++)
#pragma unroll
            for (int b2 = 0; b2 < 4; b2++) {
                int i = ti + a, j = tj + b2;
                sGL[i][j] = (j <= i) ? r[a][b2] * expf(smn[i] - scum[j]) : 0.f;
            }
    }
    // norm_diag
    if (tid < 64) {
        float s = 0.f;
        for (int j = 0; j <= tid; j++) s += expf(smn[tid] - scum[j]);
        g_ndiag[(size_t)bh * SEQL + c * 64 + tid] = s;
    }
    __syncthreads();

    // Y_diag[i][p] = sum_j GL[i][j] * X[j][p]
    {
        float r[4][4];
#pragma unroll
        for (int a = 0; a < 4; a++)
#pragma unroll
            for (int b2 = 0; b2 < 4; b2++) r[a][b2] = 0.f;
        for (int j = 0; j < 64; j++) {
            float gl[4], xv[4];
#pragma unroll
            for (int a = 0; a < 4; a++) gl[a] = sGL[ti + a][j];
#pragma unroll
            for (int b2 = 0; b2 < 4; b2++) xv[b2] = sX[j][tj + b2];
#pragma unroll
            for (int a = 0; a < 4; a++)
#pragma unroll
                for (int b2 = 0; b2 < 4; b2++) r[a][b2] = fmaf(gl[a], xv[b2], r[a][b2]);
        }
#pragma unroll
        for (int a = 0; a < 4; a++)
#pragma unroll
            for (int b2 = 0; b2 < 4; b2++)
                g_Ydiag[base + (size_t)(ti + a) * 64 + (tj + b2)] = r[a][b2];
    }
    // states[p][n] = sum_l (ds[l]*X[l][p]) * B[l][n]
    {
        float r[4][4];
#pragma unroll
        for (int a = 0; a < 4; a++)
#pragma unroll
            for (int b2 = 0; b2 < 4; b2++) r[a][b2] = 0.f;
        for (int l = 0; l < 64; l++) {
            float d = sds[l];
            float xv[4], bv[4];
#pragma unroll
            for (int a = 0; a < 4; a++) xv[a] = sX[l][ti + a] * d;
#pragma unroll
            for (int b2 = 0; b2 < 4; b2++) bv[b2] = sB[l][tj + b2];
#pragma unroll
            for (int a = 0; a < 4; a++)
#pragma unroll
                for (int b2 = 0; b2 < 4; b2++) r[a][b2] = fmaf(xv[a], bv[b2], r[a][b2]);
        }
        size_t sb = ((size_t)bh * NCH + c) * 4096;
#pragma unroll
        for (int a = 0; a < 4; a++)
#pragma unroll
            for (int b2 = 0; b2 < 4; b2++)
                g_states[sb + (size_t)(ti + a) * 64 + (tj + b2)] = r[a][b2];
    }
}

// --------------- chunk recurrence: renormalized sequential scan ---------------
// newstate[z] = sum_{c=1..z} exp(minc_z - cc_c) * state[c-1], cc_0=0, cc_c=sum Atot
__global__ void scan_k()
{
    int bh   = blockIdx.x >> 3;
    int part = blockIdx.x & 7;
    int tid  = threadIdx.x;  // 256
    int e0   = part * 512 + tid;
    size_t sb = (size_t)bh * NCH * 4096;

    float r0 = 0.f, r1 = 0.f;
    float minc = 0.f, cc = 0.f, nacc = 0.f;
    g_nstates[sb + e0] = 0.f;
    g_nstates[sb + e0 + 256] = 0.f;
    if (part == 0 && tid == 0) g_nnew[bh * NCH] = 0.f;
    for (int z = 0; z < 63; z++) {
        cc += g_Atot[bh * NCH + z];
        float m2 = fminf(minc, cc);
        float f = expf(m2 - minc);
        float g = expf(m2 - cc);
        r0 = r0 * f + g * g_states[sb + (size_t)z * 4096 + e0];
        r1 = r1 * f + g * g_states[sb + (size_t)z * 4096 + e0 + 256];
        minc = m2;
        g_nstates[sb + (size_t)(z + 1) * 4096 + e0] = r0;
        g_nstates[sb + (size_t)(z + 1) * 4096 + e0 + 256] = r1;
        if (part == 0 && tid == 0) {
            nacc = nacc * f + g * g_ndec[bh * NCH + z];
            g_nnew[bh * NCH + z + 1] = nacc;
        }
    }
}

// --------------- Y_off + combine + normalize ----------------------------------
__global__ __launch_bounds__(256) void yoff_k()
{
    __shared__ float sC[64][65];
    __shared__ float sS[64][65];
    __shared__ float scum[64];
    __shared__ float sdo[64];
    __shared__ float sMx;

    int bh = blockIdx.x >> 6;
    int c  = blockIdx.x & 63;
    int b  = bh >> 4;
    int h  = bh & 15;
    int tid = threadIdx.x;
    size_t baseC = ((size_t)bh * SEQL + (size_t)c * 64) * HD;
    size_t baseS = ((size_t)bh * NCH + c) * 4096;

    for (int i = tid; i < 4096; i += 256) {
        sC[i >> 6][i & 63] = g_Cm[baseC + i];
        sS[i >> 6][i & 63] = g_nstates[baseS + i];
    }
    if (tid < 64) scum[tid] = g_cumA[(size_t)bh * SEQL + c * 64 + tid];
    __syncthreads();
    if (tid == 0) {
        float mx = -1e30f;
        for (int l = 0; l < 64; l++) mx = fmaxf(mx, scum[l]);
        sMx = mx;
    }
    __syncthreads();
    if (tid < 64) sdo[tid] = expf(scum[tid] - sMx);
    __syncthreads();

    float nn = g_nnew[bh * NCH + c];
    int tl = (tid >> 4) * 4;
    int tp = (tid & 15) * 4;
    float r[4][4];
#pragma unroll
    for (int a = 0; a < 4; a++)
#pragma unroll
        for (int b2 = 0; b2 < 4; b2++) r[a][b2] = 0.f;
    for (int n = 0; n < 64; n++) {
        float cv[4], sv[4];
#pragma unroll
        for (int a = 0; a < 4; a++) cv[a] = sC[tl + a][n];
#pragma unroll
        for (int b2 = 0; b2 < 4; b2++) sv[b2] = sS[tp + b2][n];
#pragma unroll
        for (int a = 0; a < 4; a++)
#pragma unroll
            for (int b2 = 0; b2 < 4; b2++) r[a][b2] = fmaf(cv[a], sv[b2], r[a][b2]);
    }
#pragma unroll
    for (int a = 0; a < 4; a++) {
        int l = tl + a;
        float d = sdo[l];
        float nm = g_ndiag[(size_t)bh * SEQL + c * 64 + l] + nn * d;
        int s = c * 64 + l;
#pragma unroll
        for (int b2 = 0; b2 < 4; b2++) {
            int p = tp + b2;
            float y = g_Ydiag[baseC + (size_t)l * 64 + p] + d * r[a][b2];
            g_Y[((size_t)b * SEQL + s) * DMODEL + h * 64 + p] = y / nm;
        }
    }
}

// ------------------------------- launch ---------------------------------------
extern "C" void kernel_launch(void* const* d_in, const int* in_sizes, int n_in,
                              void* d_out, int out_size)
{
    const float* x   = (const float*)d_in[0];
    const float* ipw = (const float*)d_in[1];
    const float* cw  = (const float*)d_in[2];
    const float* cb  = (const float*)d_in[3];
    const float* wb  = (const float*)d_in[4];
    const float* opw = (const float*)d_in[5];
    float* out = (float*)d_out;

    float *p_xw = nullptr, *p_Y = nullptr;
    cudaGetSymbolAddress((void**)&p_xw, g_xw);
    cudaGetSymbolAddress((void**)&p_Y, g_Y);

    const int SMEM_CHUNK = 4 * 64 * 65 * 4;  // 66560 B
    cudaFuncSetAttribute(chunk_k, cudaFuncAttributeMaxDynamicSharedMemorySize, SMEM_CHUNK);

    // 1) in_proj: g_xw = x @ in_proj_w^T   [8192,3088]
    dim3 g1((DINP + 127) / 128, BSN / 128);
    sgemm_nt_k<<<g1, 256>>>(x, ipw, p_xw, BSN, DINP, DMODEL);

    // 2) conv + split
    conv_split_k<<<(BSN * CONVD + 255) / 256, 256>>>(cw, cb);

    // 3) A scale
    a_scale_k<<<(BSN * NH + 255) / 256, 256>>>(wb);

    // 4) per-chunk tiles
    chunk_k<<<BHN * NCH, 256, SMEM_CHUNK>>>();

    // 5) chunk recurrence scan
    scan_k<<<BHN * 8, 256>>>();

    // 6) off-diagonal + normalize
    yoff_k<<<BHN * NCH, 256>>>();

    // 7) out_proj: out = g_Y @ out_proj_w^T   [8192,1024]
    dim3 g2(DMODEL / 128, BSN / 128);
    sgemm_nt_k<<<g2, 256>>>(p_Y, opw, out, BSN, DMODEL, DMODEL);
}

// round 3
// speedup vs baseline: 1.8134x; 1.8134x over previous
#include <cuda_runtime.h>
#include <cuda_bf16.h>
#include <math.h>
#include <stdint.h>

#define BATCHN 2
#define SEQL   4096
#define DMODEL 1024
#define NH     16
#define HD     64
#define CHUNKL 64
#define NCH    64
#define CONVD  3072
#define DINP   3088
#define BHN    (BATCHN*NH)
#define BSN    (BATCHN*SEQL)
#define K3     3072
#define NPAD_IP 3200

// ---------------- scratch ------------------------------------------------------
__device__ float g_xw[(size_t)BSN*DINP];
__device__ float g_Cm[(size_t)BHN*SEQL*HD];
__device__ float g_Bm[(size_t)BHN*SEQL*HD];
__device__ float g_Xv[(size_t)BHN*SEQL*HD];
__device__ float g_Av[(size_t)BHN*SEQL];
__device__ float g_cumA[(size_t)BHN*SEQL];
__device__ float g_states[(size_t)BHN*NCH*HD*HD];
__device__ float g_nstates[(size_t)BHN*NCH*HD*HD];
__device__ float g_Atot[BHN*NCH];
__device__ float g_ndec[BHN*NCH];
__device__ float g_nnew[BHN*NCH];
__device__ float g_Ydiag[(size_t)BHN*SEQL*HD];
__device__ float g_ndiag[(size_t)BHN*SEQL];
__device__ float g_Y[(size_t)BSN*DMODEL];
__device__ __nv_bfloat16 g_xs[(size_t)BSN*K3];
__device__ __nv_bfloat16 g_ws[(size_t)NPAD_IP*K3];
__device__ __nv_bfloat16 g_w2s[(size_t)DMODEL*K3];
__device__ __nv_bfloat16 g_ys[(size_t)BSN*K3];

// ---------------- helpers ------------------------------------------------------
__device__ __forceinline__ uint32_t smem_u32(const void* p) {
    uint32_t a;
    asm("{ .reg .u64 t; cvta.to.shared.u64 t, %1; cvt.u32.u64 %0, t; }" : "=r"(a) : "l"(p));
    return a;
}
#define CP16(dst, src)  asm volatile("cp.async.cg.shared.global [%0], [%1], 16;" :: "r"(dst), "l"(src) : "memory")
#define CP_COMMIT()     asm volatile("cp.async.commit_group;" ::: "memory")

__device__ __forceinline__ void ldm_x4(uint32_t* r, uint32_t addr) {
    asm volatile("ldmatrix.sync.aligned.m8n8.x4.shared.b16 {%0,%1,%2,%3}, [%4];"
        : "=r"(r[0]), "=r"(r[1]), "=r"(r[2]), "=r"(r[3]) : "r"(addr));
}
__device__ __forceinline__ void ldm_x2(uint32_t* r, uint32_t addr) {
    asm volatile("ldmatrix.sync.aligned.m8n8.x2.shared.b16 {%0,%1}, [%2];"
        : "=r"(r[0]), "=r"(r[1]) : "r"(addr));
}
__device__ __forceinline__ void mma_bf16(float* c, const uint32_t* a, const uint32_t* b) {
    asm volatile("mma.sync.aligned.m16n8k16.row.col.f32.bf16.bf16.f32 "
        "{%0,%1,%2,%3},{%4,%5,%6,%7},{%8,%9},{%0,%1,%2,%3};"
        : "+f"(c[0]), "+f"(c[1]), "+f"(c[2]), "+f"(c[3])
        : "r"(a[0]), "r"(a[1]), "r"(a[2]), "r"(a[3]), "r"(b[0]), "r"(b[1]));
}

// ---------------- bf16 HMMA GEMM: C[m,n] = sum_k A[m,k] B[n,k] ------------------
// A [M,K] bf16 K-major, B [Npad,K] bf16 K-major, C fp32 [M,ldc]. K % 32 == 0.
#define BK 32
#define ROWE 40   // padded row length in bf16 elements (80B)

__global__ __launch_bounds__(256) void mma_gemm_k(
    const __nv_bfloat16* __restrict__ A, const __nv_bfloat16* __restrict__ B,
    float* __restrict__ C, int K, int Nout, int ldc)
{
    __shared__ __align__(16) __nv_bfloat16 smem[2][2][128 * ROWE];

    const int tid  = threadIdx.x;
    const int lane = tid & 31;
    const int wid  = tid >> 5;
    const int wm   = wid & 1;    // 2 warps along M
    const int wn   = wid >> 1;   // 4 warps along N
    const int bm   = blockIdx.y * 128;
    const int bn   = blockIdx.x * 128;
    const int nk   = K / BK;

    float acc[4][4][4];
#pragma unroll
    for (int i = 0; i < 4; i++)
#pragma unroll
        for (int j = 0; j < 4; j++)
#pragma unroll
            for (int e = 0; e < 4; e++) acc[i][j][e] = 0.f;

    // per-thread gmem load coords: 512 chunks of 16B per operand per stage
    const int r0 = tid >> 2;            // rows 0..63
    const int c0 = (tid & 3) * 8;       // k offset in elements

    uint32_t sbase = smem_u32(&smem[0][0][0]);
    const uint32_t stgB = 2u * 128 * ROWE * 2;  // bytes per stage (A+B)
    const uint32_t opB  = 128 * ROWE * 2;       // bytes per operand

    // ldmatrix base offsets (bytes, within operand block)
    uint32_t aoff[4], boff[4];
#pragma unroll
    for (int mi = 0; mi < 4; mi++) {
        int row = wm * 64 + mi * 16 + (lane & 15);
        aoff[mi] = (uint32_t)(row * ROWE + (lane >> 4) * 8) * 2;
    }
#pragma unroll
    for (int ni = 0; ni < 4; ni++) {
        int row = wn * 32 + ni * 8 + (lane & 7);
        boff[ni] = (uint32_t)(row * ROWE + ((lane >> 3) & 1) * 8) * 2;
    }

    // prologue: stage 0
    {
        uint32_t sa = sbase, sb = sbase + opB;
#pragma unroll
        for (int i = 0; i < 2; i++) {
            int r = r0 + i * 64;
            CP16(sa + (uint32_t)(r * ROWE + c0) * 2, A + (size_t)(bm + r) * K + c0);
            CP16(sb + (uint32_t)(r * ROWE + c0) * 2, B + (size_t)(bn + r) * K + c0);
        }
        CP_COMMIT();
    }

#pragma unroll 1
    for (int kt = 0; kt < nk; kt++) {
        const int cur = kt & 1;
        if (kt + 1 < nk) {
            const int nxt = cur ^ 1;
            const int k0 = (kt + 1) * BK;
            uint32_t sa = sbase + nxt * stgB, sb = sa + opB;
#pragma unroll
            for (int i = 0; i < 2; i++) {
                int r = r0 + i * 64;
                CP16(sa + (uint32_t)(r * ROWE + c0) * 2, A + (size_t)(bm + r) * K + k0 + c0);
                CP16(sb + (uint32_t)(r * ROWE + c0) * 2, B + (size_t)(bn + r) * K + k0 + c0);
            }
            CP_COMMIT();
            asm volatile("cp.async.wait_group 1;" ::: "memory");
        } else {
            asm volatile("cp.async.wait_group 0;" ::: "memory");
        }
        __syncthreads();

        uint32_t sa = sbase + cur * stgB, sb = sa + opB;
#pragma unroll
        for (int ks = 0; ks < 2; ks++) {
            uint32_t kadd = (uint32_t)(ks * 16) * 2;
            uint32_t a[4][4], b[4][2];
#pragma unroll
            for (int mi = 0; mi < 4; mi++) ldm_x4(a[mi], sa + aoff[mi] + kadd);
#pragma unroll
            for (int ni = 0; ni < 4; ni++) ldm_x2(b[ni], sb + boff[ni] + kadd);
#pragma unroll
            for (int mi = 0; mi < 4; mi++)
#pragma unroll
                for (int ni = 0; ni < 4; ni++)
                    mma_bf16(acc[mi][ni], a[mi], b[ni]);
        }
        __syncthreads();
    }

    // epilogue
#pragma unroll
    for (int mi = 0; mi < 4; mi++) {
        int row = bm + wm * 64 + mi * 16 + (lane >> 2);
#pragma unroll
        for (int ni = 0; ni < 4; ni++) {
            int col = bn + wn * 32 + ni * 8 + (lane & 3) * 2;
            if (col < Nout) {
                *(float2*)(C + (size_t)row * ldc + col)       = make_float2(acc[mi][ni][0], acc[mi][ni][1]);
                *(float2*)(C + (size_t)(row + 8) * ldc + col) = make_float2(acc[mi][ni][2], acc[mi][ni][3]);
            }
        }
    }
}

// ---------------- fp32 -> bf16 hi/lo split --------------------------------------
__global__ void split_k(const float* __restrict__ src, __nv_bfloat16* __restrict__ dst,
                        int rows, int Kin, int rowsPad, int mode)
{
    int gi = blockIdx.x * blockDim.x + threadIdx.x;
    if (gi >= rowsPad * Kin) return;
    int r = gi / Kin, k = gi % Kin;
    float v = (r < rows) ? src[(size_t)r * Kin + k] : 0.f;
    __nv_bfloat16 hi = __float2bfloat16(v);
    __nv_bfloat16 lo = __float2bfloat16(v - __bfloat162float(hi));
    size_t b = (size_t)r * (3 * Kin) + k;
    dst[b] = hi;
    dst[b + Kin]     = mode ? lo : hi;
    dst[b + 2 * Kin] = mode ? hi : lo;
}

// --------------- depthwise causal conv + split ----------------------------------
__global__ void conv_split_k(const float* __restrict__ cw, const float* __restrict__ cb)
{
    int gi = blockIdx.x * blockDim.x + threadIdx.x;
    if (gi >= BSN * CONVD) return;
    int ch = gi % CONVD;
    int bs = gi / CONVD;
    int s  = bs % SEQL;
    int b  = bs / SEQL;
    float acc = cb[ch];
#pragma unroll
    for (int k = 0; k < 4; k++) {
        int ss = s - 3 + k;
        if (ss >= 0)
            acc = fmaf(g_xw[(size_t)(b * SEQL + ss) * DINP + ch], cw[ch * 4 + k], acc);
    }
    int sect = ch >> 10;
    int h = (ch & 1023) >> 6;
    int n = ch & 63;
    float* dst = (sect == 0) ? g_Cm : (sect == 1) ? g_Bm : g_Xv;
    dst[((size_t)(b * NH + h) * SEQL + s) * HD + n] = acc;
}

__global__ void a_scale_k(const float* __restrict__ w_base)
{
    int gi = blockIdx.x * blockDim.x + threadIdx.x;
    if (gi >= BSN * NH) return;
    int h  = gi % NH;
    int bs = gi / NH;
    int s  = bs % SEQL;
    int b  = bs / SEQL;
    g_Av[((size_t)(b * NH + h)) * SEQL + s] = g_xw[(size_t)bs * DINP + CONVD + h] * w_base[h];
}

// --------------- per-chunk tile kernel -------------------------------------------
__global__ __launch_bounds__(256) void chunk_k()
{
    extern __shared__ float sh[];
    float (*sC)[65]  = (float(*)[65])sh;
    float (*sB)[65]  = (float(*)[65])(sh + 64 * 65);
    float (*sX)[65]  = (float(*)[65])(sh + 2 * 64 * 65);
    float (*sGL)[65] = (float(*)[65])(sh + 3 * 64 * 65);
    __shared__ float scum[64];
    __shared__ float smn[64];
    __shared__ float sds[64];

    int bh = blockIdx.x >> 6;
    int c  = blockIdx.x & 63;
    int tid = threadIdx.x;
    size_t base = ((size_t)bh * SEQL + (size_t)c * CHUNKL) * HD;

    for (int i = tid; i < 64 * 64; i += 256) {
        int l = i >> 6, n = i & 63;
        sC[l][n] = g_Cm[base + i];
        sB[l][n] = g_Bm[base + i];
        sX[l][n] = g_Xv[base + i];
    }
    if (tid == 0) {
        float cum = 0.f, mpre = 1e30f;
        for (int l = 0; l < 64; l++) {
            cum += g_Av[(size_t)bh * SEQL + c * 64 + l];
            scum[l] = cum;
            mpre = fminf(mpre, cum);
            smn[l] = mpre;
            g_cumA[(size_t)bh * SEQL + c * 64 + l] = cum;
        }
        g_Atot[bh * NCH + c] = cum;
        float nd = 0.f;
        for (int l = 0; l < 64; l++) { sds[l] = expf(mpre - scum[l]); nd += sds[l]; }
        g_ndec[bh * NCH + c] = nd;
    }
    __syncthreads();

    int tj = (tid & 15) * 4;
    int ti = (tid >> 4) * 4;

    {
        float r[4][4];
#pragma unroll
        for (int a = 0; a < 4; a++)
#pragma unroll
            for (int b2 = 0; b2 < 4; b2++) r[a][b2] = 0.f;
        for (int n = 0; n < 64; n++) {
            float cv[4], bv[4];
#pragma unroll
            for (int a = 0; a < 4; a++) cv[a] = sC[ti + a][n];
#pragma unroll
            for (int b2 = 0; b2 < 4; b2++) bv[b2] = sB[tj + b2][n];
#pragma unroll
            for (int a = 0; a < 4; a++)
#pragma unroll
                for (int b2 = 0; b2 < 4; b2++) r[a][b2] = fmaf(cv[a], bv[b2], r[a][b2]);
        }
#pragma unroll
        for (int a = 0; a < 4; a++)
#pragma unroll
            for (int b2 = 0; b2 < 4; b2++) {
                int i = ti + a, j = tj + b2;
                sGL[i][j] = (j <= i) ? r[a][b2] * expf(smn[i] - scum[j]) : 0.f;
            }
    }
    if (tid < 64) {
        float s = 0.f;
        for (int j = 0; j <= tid; j++) s += expf(smn[tid] - scum[j]);
        g_ndiag[(size_t)bh * SEQL + c * 64 + tid] = s;
    }
    __syncthreads();

    {
        float r[4][4];
#pragma unroll
        for (int a = 0; a < 4; a++)
#pragma unroll
            for (int b2 = 0; b2 < 4; b2++) r[a][b2] = 0.f;
        for (int j = 0; j < 64; j++) {
            float gl[4], xv[4];
#pragma unroll
            for (int a = 0; a < 4; a++) gl[a] = sGL[ti + a][j];
#pragma unroll
            for (int b2 = 0; b2 < 4; b2++) xv[b2] = sX[j][tj + b2];
#pragma unroll
            for (int a = 0; a < 4; a++)
#pragma unroll
                for (int b2 = 0; b2 < 4; b2++) r[a][b2] = fmaf(gl[a], xv[b2], r[a][b2]);
        }
#pragma unroll
        for (int a = 0; a < 4; a++)
#pragma unroll
            for (int b2 = 0; b2 < 4; b2++)
                g_Ydiag[base + (size_t)(ti + a) * 64 + (tj + b2)] = r[a][b2];
    }
    {
        float r[4][4];
#pragma unroll
        for (int a = 0; a < 4; a++)
#pragma unroll
            for (int b2 = 0; b2 < 4; b2++) r[a][b2] = 0.f;
        for (int l = 0; l < 64; l++) {
            float d = sds[l];
            float xv[4], bv[4];
#pragma unroll
            for (int a = 0; a < 4; a++) xv[a] = sX[l][ti + a] * d;
#pragma unroll
            for (int b2 = 0; b2 < 4; b2++) bv[b2] = sB[l][tj + b2];
#pragma unroll
            for (int a = 0; a < 4; a++)
#pragma unroll
                for (int b2 = 0; b2 < 4; b2++) r[a][b2] = fmaf(xv[a], bv[b2], r[a][b2]);
        }
        size_t sb = ((size_t)bh * NCH + c) * 4096;
#pragma unroll
        for (int a = 0; a < 4; a++)
#pragma unroll
            for (int b2 = 0; b2 < 4; b2++)
                g_states[sb + (size_t)(ti + a) * 64 + (tj + b2)] = r[a][b2];
    }
}

// --------------- chunk recurrence scan --------------------------------------------
__global__ void scan_k()
{
    int bh   = blockIdx.x >> 3;
    int part = blockIdx.x & 7;
    int tid  = threadIdx.x;
    int e0   = part * 512 + tid;
    size_t sb = (size_t)bh * NCH * 4096;

    float r0 = 0.f, r1 = 0.f;
    float minc = 0.f, cc = 0.f, nacc = 0.f;
    g_nstates[sb + e0] = 0.f;
    g_nstates[sb + e0 + 256] = 0.f;
    if (part == 0 && tid == 0) g_nnew[bh * NCH] = 0.f;
    for (int z = 0; z < 63; z++) {
        cc += g_Atot[bh * NCH + z];
        float m2 = fminf(minc, cc);
        float f = expf(m2 - minc);
        float g = expf(m2 - cc);
        r0 = r0 * f + g * g_states[sb + (size_t)z * 4096 + e0];
        r1 = r1 * f + g * g_states[sb + (size_t)z * 4096 + e0 + 256];
        minc = m2;
        g_nstates[sb + (size_t)(z + 1) * 4096 + e0] = r0;
        g_nstates[sb + (size_t)(z + 1) * 4096 + e0 + 256] = r1;
        if (part == 0 && tid == 0) {
            nacc = nacc * f + g * g_ndec[bh * NCH + z];
            g_nnew[bh * NCH + z + 1] = nacc;
        }
    }
}

// --------------- Y_off + combine + normalize ---------------------------------------
__global__ __launch_bounds__(256) void yoff_k()
{
    __shared__ float sC[64][65];
    __shared__ float sS[64][65];
    __shared__ float scum[64];
    __shared__ float sdo[64];
    __shared__ float sMx;

    int bh = blockIdx.x >> 6;
    int c  = blockIdx.x & 63;
    int b  = bh >> 4;
    int h  = bh & 15;
    int tid = threadIdx.x;
    size_t baseC = ((size_t)bh * SEQL + (size_t)c * 64) * HD;
    size_t baseS = ((size_t)bh * NCH + c) * 4096;

    for (int i = tid; i < 4096; i += 256) {
        sC[i >> 6][i & 63] = g_Cm[baseC + i];
        sS[i >> 6][i & 63] = g_nstates[baseS + i];
    }
    if (tid < 64) scum[tid] = g_cumA[(size_t)bh * SEQL + c * 64 + tid];
    __syncthreads();
    if (tid == 0) {
        float mx = -1e30f;
        for (int l = 0; l < 64; l++) mx = fmaxf(mx, scum[l]);
        sMx = mx;
    }
    __syncthreads();
    if (tid < 64) sdo[tid] = expf(scum[tid] - sMx);
    __syncthreads();

    float nn = g_nnew[bh * NCH + c];
    int tl = (tid >> 4) * 4;
    int tp = (tid & 15) * 4;
    float r[4][4];
#pragma unroll
    for (int a = 0; a < 4; a++)
#pragma unroll
        for (int b2 = 0; b2 < 4; b2++) r[a][b2] = 0.f;
    for (int n = 0; n < 64; n++) {
        float cv[4], sv[4];
#pragma unroll
        for (int a = 0; a < 4; a++) cv[a] = sC[tl + a][n];
#pragma unroll
        for (int b2 = 0; b2 < 4; b2++) sv[b2] = sS[tp + b2][n];
#pragma unroll
        for (int a = 0; a < 4; a++)
#pragma unroll
            for (int b2 = 0; b2 < 4; b2++) r[a][b2] = fmaf(cv[a], sv[b2], r[a][b2]);
    }
#pragma unroll
    for (int a = 0; a < 4; a++) {
        int l = tl + a;
        float d = sdo[l];
        float nm = g_ndiag[(size_t)bh * SEQL + c * 64 + l] + nn * d;
        int s = c * 64 + l;
#pragma unroll
        for (int b2 = 0; b2 < 4; b2++) {
            int p = tp + b2;
            float y = g_Ydiag[baseC + (size_t)l * 64 + p] + d * r[a][b2];
            g_Y[((size_t)b * SEQL + s) * DMODEL + h * 64 + p] = y / nm;
        }
    }
}

// ------------------------------- launch ---------------------------------------------
extern "C" void kernel_launch(void* const* d_in, const int* in_sizes, int n_in,
                              void* d_out, int out_size)
{
    const float* x   = (const float*)d_in[0];
    const float* ipw = (const float*)d_in[1];
    const float* cw  = (const float*)d_in[2];
    const float* cb  = (const float*)d_in[3];
    const float* wb  = (const float*)d_in[4];
    const float* opw = (const float*)d_in[5];
    float* out = (float*)d_out;

    float *p_xw = nullptr, *p_Y = nullptr;
    __nv_bfloat16 *p_xs, *p_ws, *p_w2s, *p_ys;
    cudaGetSymbolAddress((void**)&p_xw, g_xw);
    cudaGetSymbolAddress((void**)&p_Y, g_Y);
    cudaGetSymbolAddress((void**)&p_xs, g_xs);
    cudaGetSymbolAddress((void**)&p_ws, g_ws);
    cudaGetSymbolAddress((void**)&p_w2s, g_w2s);
    cudaGetSymbolAddress((void**)&p_ys, g_ys);

    const int SMEM_CHUNK = 4 * 64 * 65 * 4;
    cudaFuncSetAttribute(chunk_k, cudaFuncAttributeMaxDynamicSharedMemorySize, SMEM_CHUNK);

    // 0) bf16 splits
    split_k<<<(BSN * DMODEL + 255) / 256, 256>>>(x, p_xs, BSN, DMODEL, BSN, 0);
    split_k<<<(NPAD_IP * DMODEL + 255) / 256, 256>>>(ipw, p_ws, DINP, DMODEL, NPAD_IP, 1);
    split_k<<<(DMODEL * DMODEL + 255) / 256, 256>>>(opw, p_w2s, DMODEL, DMODEL, DMODEL, 1);

    // 1) in_proj via HMMA: g_xw[8192,3088] = xs @ ws^T
    {
        dim3 g(NPAD_IP / 128, BSN / 128);
        mma_gemm_k<<<g, 256>>>(p_xs, p_ws, p_xw, K3, DINP, DINP);
    }

    // 2) conv + split
    conv_split_k<<<(BSN * CONVD + 255) / 256, 256>>>(cw, cb);

    // 3) A scale
    a_scale_k<<<(BSN * NH + 255) / 256, 256>>>(wb);

    // 4) per-chunk tiles
    chunk_k<<<BHN * NCH, 256, SMEM_CHUNK>>>();

    // 5) chunk recurrence scan
    scan_k<<<BHN * 8, 256>>>();

    // 6) off-diagonal + normalize
    yoff_k<<<BHN * NCH, 256>>>();

    // 7) out_proj via HMMA
    split_k<<<(BSN * DMODEL + 255) / 256, 256>>>(p_Y, p_ys, BSN, DMODEL, BSN, 0);
    {
        dim3 g(DMODEL / 128, BSN / 128);
        mma_gemm_k<<<g, 256>>>(p_ys, p_w2s, out, K3, DMODEL, DMODEL);
    }
}

// round 4
// speedup vs baseline: 1.8491x; 1.0197x over previous
#include <cuda_runtime.h>
#include <cuda_bf16.h>
#include <math.h>
#include <stdint.h>

#define BATCHN 2
#define SEQL   4096
#define DMODEL 1024
#define NH     16
#define HD     64
#define CHUNKL 64
#define NCH    64
#define CONVD  3072
#define DINP   3088
#define BHN    (BATCHN*NH)
#define BSN    (BATCHN*SEQL)
#define K3     3072
#define NPAD_IP 3200

// ---------------- scratch ------------------------------------------------------
__device__ float g_xw[(size_t)BSN*DINP];
__device__ float g_Cm[(size_t)BHN*SEQL*HD];
__device__ float g_Bm[(size_t)BHN*SEQL*HD];
__device__ float g_Xv[(size_t)BHN*SEQL*HD];
__device__ float g_Av[(size_t)BHN*SEQL];
__device__ float g_cumA[(size_t)BHN*SEQL];
__device__ float g_states[(size_t)BHN*NCH*HD*HD];
__device__ float g_nstates[(size_t)BHN*NCH*HD*HD];
__device__ float g_Atot[BHN*NCH];
__device__ float g_ndec[BHN*NCH];
__device__ float g_nnew[BHN*NCH];
__device__ float g_Ydiag[(size_t)BHN*SEQL*HD];
__device__ float g_ndiag[(size_t)BHN*SEQL];
__device__ float g_Y[(size_t)BSN*DMODEL];
__device__ __nv_bfloat16 g_xs[(size_t)BSN*K3];
__device__ __nv_bfloat16 g_ws[(size_t)NPAD_IP*K3];
__device__ __nv_bfloat16 g_w2s[(size_t)DMODEL*K3];
__device__ __nv_bfloat16 g_ys[(size_t)BSN*K3];

// ---------------- helpers ------------------------------------------------------
__device__ __forceinline__ uint32_t smem_u32(const void* p) {
    uint32_t a;
    asm("{ .reg .u64 t; cvta.to.shared.u64 t, %1; cvt.u32.u64 %0, t; }" : "=r"(a) : "l"(p));
    return a;
}
#define CP16(dst, src)  asm volatile("cp.async.cg.shared.global [%0], [%1], 16;" :: "r"(dst), "l"(src) : "memory")
#define CP_COMMIT()     asm volatile("cp.async.commit_group;" ::: "memory")

__device__ __forceinline__ void ldm_x4(uint32_t* r, uint32_t addr) {
    asm volatile("ldmatrix.sync.aligned.m8n8.x4.shared.b16 {%0,%1,%2,%3}, [%4];"
        : "=r"(r[0]), "=r"(r[1]), "=r"(r[2]), "=r"(r[3]) : "r"(addr));
}
__device__ __forceinline__ void ldm_x2(uint32_t* r, uint32_t addr) {
    asm volatile("ldmatrix.sync.aligned.m8n8.x2.shared.b16 {%0,%1}, [%2];"
        : "=r"(r[0]), "=r"(r[1]) : "r"(addr));
}
__device__ __forceinline__ void mma_bf16(float* c, const uint32_t* a, const uint32_t* b) {
    asm volatile("mma.sync.aligned.m16n8k16.row.col.f32.bf16.bf16.f32 "
        "{%0,%1,%2,%3},{%4,%5,%6,%7},{%8,%9},{%0,%1,%2,%3};"
        : "+f"(c[0]), "+f"(c[1]), "+f"(c[2]), "+f"(c[3])
        : "r"(a[0]), "r"(a[1]), "r"(a[2]), "r"(a[3]), "r"(b[0]), "r"(b[1]));
}

// ---------------- bf16 HMMA GEMM: C[m,n] = sum_k A[m,k] B[n,k] ------------------
// 4-stage cp.async pipeline, one __syncthreads per BK iteration.
#define BK    32
#define ROWE  40       // padded row (80B): conflict-free ldmatrix
#define NSTG  4
#define STGB  (2u * 128 * ROWE * 2)   // bytes per stage (A+B) = 20480
#define OPB   (128u * ROWE * 2)       // bytes per operand    = 10240

__global__ __launch_bounds__(256) void mma_gemm_k(
    const __nv_bfloat16* __restrict__ A, const __nv_bfloat16* __restrict__ B,
    float* __restrict__ C, int K, int Nout, int ldc)
{
    extern __shared__ __align__(16) __nv_bfloat16 dsm[];

    const int tid  = threadIdx.x;
    const int lane = tid & 31;
    const int wid  = tid >> 5;
    const int wm   = wid & 1;
    const int wn   = wid >> 1;
    const int bm   = blockIdx.y * 128;
    const int bn   = blockIdx.x * 128;
    const int nk   = K / BK;

    float acc[4][4][4];
#pragma unroll
    for (int i = 0; i < 4; i++)
#pragma unroll
        for (int j = 0; j < 4; j++)
#pragma unroll
            for (int e = 0; e < 4; e++) acc[i][j][e] = 0.f;

    const int r0 = tid >> 2;
    const int c0 = (tid & 3) * 8;
    uint32_t sbase = smem_u32(dsm);

    uint32_t aoff[4], boff[4];
#pragma unroll
    for (int mi = 0; mi < 4; mi++) {
        int row = wm * 64 + mi * 16 + (lane & 15);
        aoff[mi] = (uint32_t)(row * ROWE + (lane >> 4) * 8) * 2;
    }
#pragma unroll
    for (int ni = 0; ni < 4; ni++) {
        int row = wn * 32 + ni * 8 + (lane & 7);
        boff[ni] = (uint32_t)(row * ROWE + ((lane >> 3) & 1) * 8) * 2;
    }

    // prologue: stages 0..2
#pragma unroll
    for (int j = 0; j < 3; j++) {
        uint32_t sa = sbase + j * STGB, sb = sa + OPB;
        int k0 = j * BK;
#pragma unroll
        for (int i = 0; i < 2; i++) {
            int r = r0 + i * 64;
            CP16(sa + (uint32_t)(r * ROWE + c0) * 2, A + (size_t)(bm + r) * K + k0 + c0);
            CP16(sb + (uint32_t)(r * ROWE + c0) * 2, B + (size_t)(bn + r) * K + k0 + c0);
        }
        CP_COMMIT();
    }

#pragma unroll 1
    for (int kt = 0; kt < nk; kt++) {
        asm volatile("cp.async.wait_group 2;" ::: "memory");
        __syncthreads();

        // issue loads for kt+3 (into stage read at kt-1; safe past barrier)
        int jn = kt + 3;
        if (jn < nk) {
            uint32_t sa = sbase + (uint32_t)(jn & 3) * STGB, sb = sa + OPB;
            int k0 = jn * BK;
#pragma unroll
            for (int i = 0; i < 2; i++) {
                int r = r0 + i * 64;
                CP16(sa + (uint32_t)(r * ROWE + c0) * 2, A + (size_t)(bm + r) * K + k0 + c0);
                CP16(sb + (uint32_t)(r * ROWE + c0) * 2, B + (size_t)(bn + r) * K + k0 + c0);
            }
        }
        CP_COMMIT();  // always exactly one group per iter (may be empty)

        uint32_t sa = sbase + (uint32_t)(kt & 3) * STGB, sb = sa + OPB;
#pragma unroll
        for (int ks = 0; ks < 2; ks++) {
            uint32_t kadd = (uint32_t)(ks * 16) * 2;
            uint32_t a[4][4], b[4][2];
#pragma unroll
            for (int mi = 0; mi < 4; mi++) ldm_x4(a[mi], sa + aoff[mi] + kadd);
#pragma unroll
            for (int ni = 0; ni < 4; ni++) ldm_x2(b[ni], sb + boff[ni] + kadd);
#pragma unroll
            for (int mi = 0; mi < 4; mi++)
#pragma unroll
                for (int ni = 0; ni < 4; ni++)
                    mma_bf16(acc[mi][ni], a[mi], b[ni]);
        }
    }

    // epilogue
#pragma unroll
    for (int mi = 0; mi < 4; mi++) {
        int row = bm + wm * 64 + mi * 16 + (lane >> 2);
#pragma unroll
        for (int ni = 0; ni < 4; ni++) {
            int col = bn + wn * 32 + ni * 8 + (lane & 3) * 2;
            if (col < Nout) {
                *(float2*)(C + (size_t)row * ldc + col)       = make_float2(acc[mi][ni][0], acc[mi][ni][1]);
                *(float2*)(C + (size_t)(row + 8) * ldc + col) = make_float2(acc[mi][ni][2], acc[mi][ni][3]);
            }
        }
    }
}

// ---------------- fp32 -> bf16 hi/lo split --------------------------------------
__global__ void split_k(const float* __restrict__ src, __nv_bfloat16* __restrict__ dst,
                        int rows, int Kin, int rowsPad, int mode)
{
    int gi = blockIdx.x * blockDim.x + threadIdx.x;
    if (gi >= rowsPad * Kin) return;
    int r = gi / Kin, k = gi % Kin;
    float v = (r < rows) ? src[(size_t)r * Kin + k] : 0.f;
    __nv_bfloat16 hi = __float2bfloat16(v);
    __nv_bfloat16 lo = __float2bfloat16(v - __bfloat162float(hi));
    size_t b = (size_t)r * (3 * Kin) + k;
    dst[b] = hi;
    dst[b + Kin]     = mode ? lo : hi;
    dst[b + 2 * Kin] = mode ? hi : lo;
}

// --------------- depthwise causal conv + split ----------------------------------
__global__ void conv_split_k(const float* __restrict__ cw, const float* __restrict__ cb)
{
    int gi = blockIdx.x * blockDim.x + threadIdx.x;
    if (gi >= BSN * CONVD) return;
    int ch = gi % CONVD;
    int bs = gi / CONVD;
    int s  = bs % SEQL;
    int b  = bs / SEQL;
    float acc = cb[ch];
#pragma unroll
    for (int k = 0; k < 4; k++) {
        int ss = s - 3 + k;
        if (ss >= 0)
            acc = fmaf(g_xw[(size_t)(b * SEQL + ss) * DINP + ch], cw[ch * 4 + k], acc);
    }
    int sect = ch >> 10;
    int h = (ch & 1023) >> 6;
    int n = ch & 63;
    float* dst = (sect == 0) ? g_Cm : (sect == 1) ? g_Bm : g_Xv;
    dst[((size_t)(b * NH + h) * SEQL + s) * HD + n] = acc;
}

__global__ void a_scale_k(const float* __restrict__ w_base)
{
    int gi = blockIdx.x * blockDim.x + threadIdx.x;
    if (gi >= BSN * NH) return;
    int h  = gi % NH;
    int bs = gi / NH;
    int s  = bs % SEQL;
    int b  = bs / SEQL;
    g_Av[((size_t)(b * NH + h)) * SEQL + s] = g_xw[(size_t)bs * DINP + CONVD + h] * w_base[h];
}

// --------------- per-chunk tile kernel -------------------------------------------
__global__ __launch_bounds__(256) void chunk_k()
{
    extern __shared__ float sh[];
    float (*sC)[65]  = (float(*)[65])sh;
    float (*sB)[65]  = (float(*)[65])(sh + 64 * 65);
    float (*sX)[65]  = (float(*)[65])(sh + 2 * 64 * 65);
    float (*sGL)[65] = (float(*)[65])(sh + 3 * 64 * 65);
    __shared__ float scum[64];
    __shared__ float smn[64];
    __shared__ float sds[64];

    int bh = blockIdx.x >> 6;
    int c  = blockIdx.x & 63;
    int tid = threadIdx.x;
    size_t base = ((size_t)bh * SEQL + (size_t)c * CHUNKL) * HD;
    size_t abase = (size_t)bh * SEQL + c * 64;

    for (int i = tid; i < 64 * 64; i += 256) {
        int l = i >> 6, n = i & 63;
        sC[l][n] = g_Cm[base + i];
        sB[l][n] = g_Bm[base + i];
        sX[l][n] = g_Xv[base + i];
    }
    // warp 0: parallel cumsum + prefix-min + decay-states
    if (tid < 32) {
        float v0 = g_Av[abase + 2 * tid];
        float v1 = g_Av[abase + 2 * tid + 1];
        float s = v0 + v1;
#pragma unroll
        for (int o = 1; o < 32; o <<= 1) {
            float t = __shfl_up_sync(0xffffffffu, s, o);
            if (tid >= o) s += t;
        }
        float c1 = s, cc0 = s - v1;
        scum[2 * tid] = cc0; scum[2 * tid + 1] = c1;
        g_cumA[abase + 2 * tid] = cc0;
        g_cumA[abase + 2 * tid + 1] = c1;
        float mm = fminf(cc0, c1);
#pragma unroll
        for (int o = 1; o < 32; o <<= 1) {
            float t = __shfl_up_sync(0xffffffffu, mm, o);
            if (tid >= o) mm = fminf(mm, t);
        }
        float prev = __shfl_up_sync(0xffffffffu, mm, 1);
        if (tid == 0) prev = 1e30f;
        smn[2 * tid]     = fminf(prev, cc0);
        smn[2 * tid + 1] = fminf(prev, fminf(cc0, c1));
        float mtot = __shfl_sync(0xffffffffu, mm, 31);
        float d0 = expf(mtot - cc0), d1 = expf(mtot - c1);
        sds[2 * tid] = d0; sds[2 * tid + 1] = d1;
        float nd = d0 + d1;
#pragma unroll
        for (int o = 16; o; o >>= 1) nd += __shfl_xor_sync(0xffffffffu, nd, o);
        float ctot = __shfl_sync(0xffffffffu, c1, 31);
        if (tid == 0) { g_Atot[bh * NCH + c] = ctot; g_ndec[bh * NCH + c] = nd; }
    }
    __syncthreads();

    int tj = (tid & 15) * 4;
    int ti = (tid >> 4) * 4;

    {
        float r[4][4];
#pragma unroll
        for (int a = 0; a < 4; a++)
#pragma unroll
            for (int b2 = 0; b2 < 4; b2++) r[a][b2] = 0.f;
        for (int n = 0; n < 64; n++) {
            float cv[4], bv[4];
#pragma unroll
            for (int a = 0; a < 4; a++) cv[a] = sC[ti + a][n];
#pragma unroll
            for (int b2 = 0; b2 < 4; b2++) bv[b2] = sB[tj + b2][n];
#pragma unroll
            for (int a = 0; a < 4; a++)
#pragma unroll
                for (int b2 = 0; b2 < 4; b2++) r[a][b2] = fmaf(cv[a], bv[b2], r[a][b2]);
        }
#pragma unroll
        for (int a = 0; a < 4; a++)
#pragma unroll
            for (int b2 = 0; b2 < 4; b2++) {
                int i = ti + a, j = tj + b2;
                sGL[i][j] = (j <= i) ? r[a][b2] * expf(smn[i] - scum[j]) : 0.f;
            }
    }
    if (tid < 64) {
        float s = 0.f;
        for (int j = 0; j <= tid; j++) s += expf(smn[tid] - scum[j]);
        g_ndiag[abase + tid] = s;
    }
    __syncthreads();

    {
        float r[4][4];
#pragma unroll
        for (int a = 0; a < 4; a++)
#pragma unroll
            for (int b2 = 0; b2 < 4; b2++) r[a][b2] = 0.f;
        for (int j = 0; j < 64; j++) {
            float gl[4], xv[4];
#pragma unroll
            for (int a = 0; a < 4; a++) gl[a] = sGL[ti + a][j];
#pragma unroll
            for (int b2 = 0; b2 < 4; b2++) xv[b2] = sX[j][tj + b2];
#pragma unroll
            for (int a = 0; a < 4; a++)
#pragma unroll
                for (int b2 = 0; b2 < 4; b2++) r[a][b2] = fmaf(gl[a], xv[b2], r[a][b2]);
        }
#pragma unroll
        for (int a = 0; a < 4; a++)
#pragma unroll
            for (int b2 = 0; b2 < 4; b2++)
                g_Ydiag[base + (size_t)(ti + a) * 64 + (tj + b2)] = r[a][b2];
    }
    {
        float r[4][4];
#pragma unroll
        for (int a = 0; a < 4; a++)
#pragma unroll
            for (int b2 = 0; b2 < 4; b2++) r[a][b2] = 0.f;
        for (int l = 0; l < 64; l++) {
            float d = sds[l];
            float xv[4], bv[4];
#pragma unroll
            for (int a = 0; a < 4; a++) xv[a] = sX[l][ti + a] * d;
#pragma unroll
            for (int b2 = 0; b2 < 4; b2++) bv[b2] = sB[l][tj + b2];
#pragma unroll
            for (int a = 0; a < 4; a++)
#pragma unroll
                for (int b2 = 0; b2 < 4; b2++) r[a][b2] = fmaf(xv[a], bv[b2], r[a][b2]);
        }
        size_t sb = ((size_t)bh * NCH + c) * 4096;
#pragma unroll
        for (int a = 0; a < 4; a++)
#pragma unroll
            for (int b2 = 0; b2 < 4; b2++)
                g_states[sb + (size_t)(ti + a) * 64 + (tj + b2)] = r[a][b2];
    }
}

// --------------- chunk recurrence scan --------------------------------------------
__global__ void scan_k()
{
    int bh   = blockIdx.x >> 3;
    int part = blockIdx.x & 7;
    int tid  = threadIdx.x;
    int e0   = part * 512 + tid;
    size_t sb = (size_t)bh * NCH * 4096;

    float r0 = 0.f, r1 = 0.f;
    float minc = 0.f, cc = 0.f, nacc = 0.f;
    g_nstates[sb + e0] = 0.f;
    g_nstates[sb + e0 + 256] = 0.f;
    if (part == 0 && tid == 0) g_nnew[bh * NCH] = 0.f;
    for (int z = 0; z < 63; z++) {
        cc += g_Atot[bh * NCH + z];
        float m2 = fminf(minc, cc);
        float f = expf(m2 - minc);
        float g = expf(m2 - cc);
        r0 = r0 * f + g * g_states[sb + (size_t)z * 4096 + e0];
        r1 = r1 * f + g * g_states[sb + (size_t)z * 4096 + e0 + 256];
        minc = m2;
        g_nstates[sb + (size_t)(z + 1) * 4096 + e0] = r0;
        g_nstates[sb + (size_t)(z + 1) * 4096 + e0 + 256] = r1;
        if (part == 0 && tid == 0) {
            nacc = nacc * f + g * g_ndec[bh * NCH + z];
            g_nnew[bh * NCH + z + 1] = nacc;
        }
    }
}

// --------------- Y_off + combine + normalize ---------------------------------------
__global__ __launch_bounds__(256) void yoff_k()
{
    __shared__ float sC[64][65];
    __shared__ float sS[64][65];
    __shared__ float scum[64];
    __shared__ float sdo[64];
    __shared__ float sMx;

    int bh = blockIdx.x >> 6;
    int c  = blockIdx.x & 63;
    int b  = bh >> 4;
    int h  = bh & 15;
    int tid = threadIdx.x;
    size_t baseC = ((size_t)bh * SEQL + (size_t)c * 64) * HD;
    size_t baseS = ((size_t)bh * NCH + c) * 4096;

    for (int i = tid; i < 4096; i += 256) {
        sC[i >> 6][i & 63] = g_Cm[baseC + i];
        sS[i >> 6][i & 63] = g_nstates[baseS + i];
    }
    if (tid < 64) scum[tid] = g_cumA[(size_t)bh * SEQL + c * 64 + tid];
    __syncthreads();
    if (tid == 0) {
        float mx = -1e30f;
        for (int l = 0; l < 64; l++) mx = fmaxf(mx, scum[l]);
        sMx = mx;
    }
    __syncthreads();
    if (tid < 64) sdo[tid] = expf(scum[tid] - sMx);
    __syncthreads();

    float nn = g_nnew[bh * NCH + c];
    int tl = (tid >> 4) * 4;
    int tp = (tid & 15) * 4;
    float r[4][4];
#pragma unroll
    for (int a = 0; a < 4; a++)
#pragma unroll
        for (int b2 = 0; b2 < 4; b2++) r[a][b2] = 0.f;
    for (int n = 0; n < 64; n++) {
        float cv[4], sv[4];
#pragma unroll
        for (int a = 0; a < 4; a++) cv[a] = sC[tl + a][n];
#pragma unroll
        for (int b2 = 0; b2 < 4; b2++) sv[b2] = sS[tp + b2][n];
#pragma unroll
        for (int a = 0; a < 4; a++)
#pragma unroll
            for (int b2 = 0; b2 < 4; b2++) r[a][b2] = fmaf(cv[a], sv[b2], r[a][b2]);
    }
#pragma unroll
    for (int a = 0; a < 4; a++) {
        int l = tl + a;
        float d = sdo[l];
        float nm = g_ndiag[(size_t)bh * SEQL + c * 64 + l] + nn * d;
        int s = c * 64 + l;
#pragma unroll
        for (int b2 = 0; b2 < 4; b2++) {
            int p = tp + b2;
            float y = g_Ydiag[baseC + (size_t)l * 64 + p] + d * r[a][b2];
            g_Y[((size_t)b * SEQL + s) * DMODEL + h * 64 + p] = y / nm;
        }
    }
}

// ------------------------------- launch ---------------------------------------------
extern "C" void kernel_launch(void* const* d_in, const int* in_sizes, int n_in,
                              void* d_out, int out_size)
{
    const float* x   = (const float*)d_in[0];
    const float* ipw = (const float*)d_in[1];
    const float* cw  = (const float*)d_in[2];
    const float* cb  = (const float*)d_in[3];
    const float* wb  = (const float*)d_in[4];
    const float* opw = (const float*)d_in[5];
    float* out = (float*)d_out;

    float *p_xw = nullptr, *p_Y = nullptr;
    __nv_bfloat16 *p_xs, *p_ws, *p_w2s, *p_ys;
    cudaGetSymbolAddress((void**)&p_xw, g_xw);
    cudaGetSymbolAddress((void**)&p_Y, g_Y);
    cudaGetSymbolAddress((void**)&p_xs, g_xs);
    cudaGetSymbolAddress((void**)&p_ws, g_ws);
    cudaGetSymbolAddress((void**)&p_w2s, g_w2s);
    cudaGetSymbolAddress((void**)&p_ys, g_ys);

    const int SMEM_CHUNK = 4 * 64 * 65 * 4;
    cudaFuncSetAttribute(chunk_k, cudaFuncAttributeMaxDynamicSharedMemorySize, SMEM_CHUNK);
    const int SMEM_GEMM = NSTG * (int)STGB;   // 81920
    cudaFuncSetAttribute(mma_gemm_k, cudaFuncAttributeMaxDynamicSharedMemorySize, SMEM_GEMM);

    // 0) bf16 splits
    split_k<<<(BSN * DMODEL + 255) / 256, 256>>>(x, p_xs, BSN, DMODEL, BSN, 0);
    split_k<<<(NPAD_IP * DMODEL + 255) / 256, 256>>>(ipw, p_ws, DINP, DMODEL, NPAD_IP, 1);
    split_k<<<(DMODEL * DMODEL + 255) / 256, 256>>>(opw, p_w2s, DMODEL, DMODEL, DMODEL, 1);

    // 1) in_proj via HMMA: g_xw[8192,3088] = xs @ ws^T
    {
        dim3 g(NPAD_IP / 128, BSN / 128);
        mma_gemm_k<<<g, 256, SMEM_GEMM>>>(p_xs, p_ws, p_xw, K3, DINP, DINP);
    }

    // 2) conv + split
    conv_split_k<<<(BSN * CONVD + 255) / 256, 256>>>(cw, cb);

    // 3) A scale
    a_scale_k<<<(BSN * NH + 255) / 256, 256>>>(wb);

    // 4) per-chunk tiles
    chunk_k<<<BHN * NCH, 256, SMEM_CHUNK>>>();

    // 5) chunk recurrence scan
    scan_k<<<BHN * 8, 256>>>();

    // 6) off-diagonal + normalize
    yoff_k<<<BHN * NCH, 256>>>();

    // 7) out_proj via HMMA
    split_k<<<(BSN * DMODEL + 255) / 256, 256>>>(p_Y, p_ys, BSN, DMODEL, BSN, 0);
    {
        dim3 g(DMODEL / 128, BSN / 128);
        mma_gemm_k<<<g, 256, SMEM_GEMM>>>(p_ys, p_w2s, out, K3, DMODEL, DMODEL);
    }
}

// round 5
// speedup vs baseline: 1.9532x; 1.0563x over previous
#include <cuda_runtime.h>
#include <cuda_bf16.h>
#include <math.h>
#include <stdint.h>

#define BATCHN 2
#define SEQL   4096
#define DMODEL 1024
#define NH     16
#define HD     64
#define CHUNKL 64
#define NCH    64
#define CONVD  3072
#define DINP   3088
#define BHN    (BATCHN*NH)
#define BSN    (BATCHN*SEQL)
#define K3     3072
#define NPAD_IP 3200

// ---------------- scratch ------------------------------------------------------
__device__ float g_xw[(size_t)BSN*DINP];
__device__ float g_Cm[(size_t)BHN*SEQL*HD];
__device__ float g_Bm[(size_t)BHN*SEQL*HD];
__device__ float g_Xv[(size_t)BHN*SEQL*HD];
__device__ float g_Av[(size_t)BHN*SEQL];
__device__ float g_cumA[(size_t)BHN*SEQL];
__device__ float g_states[(size_t)BHN*NCH*HD*HD];
__device__ float g_nstates[(size_t)BHN*NCH*HD*HD];
__device__ float g_Atot[BHN*NCH];
__device__ float g_ndec[BHN*NCH];
__device__ float g_nnew[BHN*NCH];
__device__ float g_Ydiag[(size_t)BHN*SEQL*HD];
__device__ float g_ndiag[(size_t)BHN*SEQL];
__device__ __nv_bfloat16 g_xs[(size_t)BSN*K3];
__device__ __nv_bfloat16 g_ws[(size_t)NPAD_IP*K3];
__device__ __nv_bfloat16 g_w2s[(size_t)DMODEL*K3];
__device__ __nv_bfloat16 g_ys[(size_t)BSN*K3];

// ---------------- helpers ------------------------------------------------------
__device__ __forceinline__ uint32_t smem_u32(const void* p) {
    uint32_t a;
    asm("{ .reg .u64 t; cvta.to.shared.u64 t, %1; cvt.u32.u64 %0, t; }" : "=r"(a) : "l"(p));
    return a;
}
#define CP16(dst, src)  asm volatile("cp.async.cg.shared.global [%0], [%1], 16;" :: "r"(dst), "l"(src) : "memory")
#define CP_COMMIT()     asm volatile("cp.async.commit_group;" ::: "memory")

__device__ __forceinline__ void ldm_x4(uint32_t* r, uint32_t addr) {
    asm volatile("ldmatrix.sync.aligned.m8n8.x4.shared.b16 {%0,%1,%2,%3}, [%4];"
        : "=r"(r[0]), "=r"(r[1]), "=r"(r[2]), "=r"(r[3]) : "r"(addr));
}
__device__ __forceinline__ void mma_bf16(float* c, const uint32_t* a, const uint32_t* b) {
    asm volatile("mma.sync.aligned.m16n8k16.row.col.f32.bf16.bf16.f32 "
        "{%0,%1,%2,%3},{%4,%5,%6,%7},{%8,%9},{%0,%1,%2,%3};"
        : "+f"(c[0]), "+f"(c[1]), "+f"(c[2]), "+f"(c[3])
        : "r"(a[0]), "r"(a[1]), "r"(a[2]), "r"(a[3]), "r"(b[0]), "r"(b[1]));
}

// ---------------- bf16 HMMA GEMM ------------------------------------------------
#define BK    32
#define ROWE  40
#define NSTG  4
#define STGB  (2u * 128 * ROWE * 2)
#define OPB   (128u * ROWE * 2)

__global__ __launch_bounds__(256, 2) void mma_gemm_k(
    const __nv_bfloat16* __restrict__ A, const __nv_bfloat16* __restrict__ B,
    float* __restrict__ C, int K, int Nout, int ldc)
{
    extern __shared__ __align__(16) __nv_bfloat16 dsm[];

    const int tid  = threadIdx.x;
    const int lane = tid & 31;
    const int wid  = tid >> 5;
    const int wm   = wid & 1;
    const int wn   = wid >> 1;
    const int bm   = blockIdx.y * 128;
    const int bn   = blockIdx.x * 128;
    const int nk   = K / BK;

    float acc[4][4][4];
#pragma unroll
    for (int i = 0; i < 4; i++)
#pragma unroll
        for (int j = 0; j < 4; j++)
#pragma unroll
            for (int e = 0; e < 4; e++) acc[i][j][e] = 0.f;

    const int r0 = tid >> 2;
    const int c0 = (tid & 3) * 8;
    uint32_t sbase = smem_u32(dsm);

    // A ldmatrix offsets (x4: 16×16 tile per mi)
    uint32_t aoff[4];
#pragma unroll
    for (int mi = 0; mi < 4; mi++) {
        int row = wm * 64 + mi * 16 + (lane & 15);
        aoff[mi] = (uint32_t)(row * ROWE + (lane >> 4) * 8) * 2;
    }
    // B ldmatrix offsets (x4 pair: lanes 0-15 -> ni=2*pi, lanes 16-31 -> ni=2*pi+1)
    uint32_t boffp[2];
#pragma unroll
    for (int pi = 0; pi < 2; pi++) {
        int l2  = lane & 15;
        int grp = lane >> 4;
        int row = wn * 32 + (pi * 2 + grp) * 8 + (l2 & 7);
        boffp[pi] = (uint32_t)(row * ROWE + ((l2 >> 3) & 1) * 8) * 2;
    }

    // prologue: stages 0..2
#pragma unroll
    for (int j = 0; j < 3; j++) {
        uint32_t sa = sbase + j * STGB, sb = sa + OPB;
        int k0 = j * BK;
#pragma unroll
        for (int i = 0; i < 2; i++) {
            int r = r0 + i * 64;
            CP16(sa + (uint32_t)(r * ROWE + c0) * 2, A + (size_t)(bm + r) * K + k0 + c0);
            CP16(sb + (uint32_t)(r * ROWE + c0) * 2, B + (size_t)(bn + r) * K + k0 + c0);
        }
        CP_COMMIT();
    }

#pragma unroll 1
    for (int kt = 0; kt < nk; kt++) {
        asm volatile("cp.async.wait_group 2;" ::: "memory");
        __syncthreads();

        int jn = kt + 3;
        if (jn < nk) {
            uint32_t sa = sbase + (uint32_t)(jn & 3) * STGB, sb = sa + OPB;
            int k0 = jn * BK;
#pragma unroll
            for (int i = 0; i < 2; i++) {
                int r = r0 + i * 64;
                CP16(sa + (uint32_t)(r * ROWE + c0) * 2, A + (size_t)(bm + r) * K + k0 + c0);
                CP16(sb + (uint32_t)(r * ROWE + c0) * 2, B + (size_t)(bn + r) * K + k0 + c0);
            }
        }
        CP_COMMIT();

        uint32_t sa = sbase + (uint32_t)(kt & 3) * STGB, sb = sa + OPB;

        // load ALL fragments for both ks steps, then burst MMAs
        uint32_t a[2][4][4];
        uint32_t bp[2][2][4];   // [ks][pi][4 regs = 2 ni frags]
#pragma unroll
        for (int ks = 0; ks < 2; ks++) {
            uint32_t kadd = (uint32_t)(ks * 16) * 2;
#pragma unroll
            for (int mi = 0; mi < 4; mi++) ldm_x4(a[ks][mi], sa + aoff[mi] + kadd);
#pragma unroll
            for (int pi = 0; pi < 2; pi++) ldm_x4(bp[ks][pi], sb + boffp[pi] + kadd);
        }
#pragma unroll
        for (int ks = 0; ks < 2; ks++)
#pragma unroll
            for (int mi = 0; mi < 4; mi++)
#pragma unroll
                for (int ni = 0; ni < 4; ni++)
                    mma_bf16(acc[mi][ni], a[ks][mi], &bp[ks][ni >> 1][(ni & 1) * 2]);
    }

    // epilogue
#pragma unroll
    for (int mi = 0; mi < 4; mi++) {
        int row = bm + wm * 64 + mi * 16 + (lane >> 2);
#pragma unroll
        for (int ni = 0; ni < 4; ni++) {
            int col = bn + wn * 32 + ni * 8 + (lane & 3) * 2;
            if (col < Nout) {
                *(float2*)(C + (size_t)row * ldc + col)       = make_float2(acc[mi][ni][0], acc[mi][ni][1]);
                *(float2*)(C + (size_t)(row + 8) * ldc + col) = make_float2(acc[mi][ni][2], acc[mi][ni][3]);
            }
        }
    }
}

// ---------------- fp32 -> bf16 hi/lo split --------------------------------------
__global__ void split_k(const float* __restrict__ src, __nv_bfloat16* __restrict__ dst,
                        int rows, int Kin, int rowsPad, int mode)
{
    int gi = blockIdx.x * blockDim.x + threadIdx.x;
    if (gi >= rowsPad * Kin) return;
    int r = gi / Kin, k = gi % Kin;
    float v = (r < rows) ? src[(size_t)r * Kin + k] : 0.f;
    __nv_bfloat16 hi = __float2bfloat16(v);
    __nv_bfloat16 lo = __float2bfloat16(v - __bfloat162float(hi));
    size_t b = (size_t)r * (3 * Kin) + k;
    dst[b] = hi;
    dst[b + Kin]     = mode ? lo : hi;
    dst[b + 2 * Kin] = mode ? hi : lo;
}

// --------------- depthwise causal conv + split ----------------------------------
__global__ void conv_split_k(const float* __restrict__ cw, const float* __restrict__ cb)
{
    int gi = blockIdx.x * blockDim.x + threadIdx.x;
    if (gi >= BSN * CONVD) return;
    int ch = gi % CONVD;
    int bs = gi / CONVD;
    int s  = bs % SEQL;
    int b  = bs / SEQL;
    float acc = cb[ch];
#pragma unroll
    for (int k = 0; k < 4; k++) {
        int ss = s - 3 + k;
        if (ss >= 0)
            acc = fmaf(g_xw[(size_t)(b * SEQL + ss) * DINP + ch], cw[ch * 4 + k], acc);
    }
    int sect = ch >> 10;
    int h = (ch & 1023) >> 6;
    int n = ch & 63;
    float* dst = (sect == 0) ? g_Cm : (sect == 1) ? g_Bm : g_Xv;
    dst[((size_t)(b * NH + h) * SEQL + s) * HD + n] = acc;
}

__global__ void a_scale_k(const float* __restrict__ w_base)
{
    int gi = blockIdx.x * blockDim.x + threadIdx.x;
    if (gi >= BSN * NH) return;
    int h  = gi % NH;
    int bs = gi / NH;
    int s  = bs % SEQL;
    int b  = bs / SEQL;
    g_Av[((size_t)(b * NH + h)) * SEQL + s] = g_xw[(size_t)bs * DINP + CONVD + h] * w_base[h];
}

// --------------- per-chunk tile kernel -------------------------------------------
__global__ __launch_bounds__(256) void chunk_k()
{
    extern __shared__ float sh[];
    float (*sC)[65]  = (float(*)[65])sh;
    float (*sB)[65]  = (float(*)[65])(sh + 64 * 65);
    float (*sX)[65]  = (float(*)[65])(sh + 2 * 64 * 65);
    float (*sGL)[65] = (float(*)[65])(sh + 3 * 64 * 65);
    __shared__ float scum[64];
    __shared__ float smn[64];
    __shared__ float sds[64];

    int bh = blockIdx.x >> 6;
    int c  = blockIdx.x & 63;
    int tid = threadIdx.x;
    size_t base = ((size_t)bh * SEQL + (size_t)c * CHUNKL) * HD;
    size_t abase = (size_t)bh * SEQL + c * 64;

    for (int i = tid; i < 64 * 64; i += 256) {
        int l = i >> 6, n = i & 63;
        sC[l][n] = g_Cm[base + i];
        sB[l][n] = g_Bm[base + i];
        sX[l][n] = g_Xv[base + i];
    }
    if (tid < 32) {
        float v0 = g_Av[abase + 2 * tid];
        float v1 = g_Av[abase + 2 * tid + 1];
        float s = v0 + v1;
#pragma unroll
        for (int o = 1; o < 32; o <<= 1) {
            float t = __shfl_up_sync(0xffffffffu, s, o);
            if (tid >= o) s += t;
        }
        float c1 = s, cc0 = s - v1;
        scum[2 * tid] = cc0; scum[2 * tid + 1] = c1;
        g_cumA[abase + 2 * tid] = cc0;
        g_cumA[abase + 2 * tid + 1] = c1;
        float mm = fminf(cc0, c1);
#pragma unroll
        for (int o = 1; o < 32; o <<= 1) {
            float t = __shfl_up_sync(0xffffffffu, mm, o);
            if (tid >= o) mm = fminf(mm, t);
        }
        float prev = __shfl_up_sync(0xffffffffu, mm, 1);
        if (tid == 0) prev = 1e30f;
        smn[2 * tid]     = fminf(prev, cc0);
        smn[2 * tid + 1] = fminf(prev, fminf(cc0, c1));
        float mtot = __shfl_sync(0xffffffffu, mm, 31);
        float d0 = expf(mtot - cc0), d1 = expf(mtot - c1);
        sds[2 * tid] = d0; sds[2 * tid + 1] = d1;
        float nd = d0 + d1;
#pragma unroll
        for (int o = 16; o; o >>= 1) nd += __shfl_xor_sync(0xffffffffu, nd, o);
        float ctot = __shfl_sync(0xffffffffu, c1, 31);
        if (tid == 0) { g_Atot[bh * NCH + c] = ctot; g_ndec[bh * NCH + c] = nd; }
    }
    __syncthreads();

    int tj = (tid & 15) * 4;
    int ti = (tid >> 4) * 4;

    {
        float r[4][4];
#pragma unroll
        for (int a = 0; a < 4; a++)
#pragma unroll
            for (int b2 = 0; b2 < 4; b2++) r[a][b2] = 0.f;
        for (int n = 0; n < 64; n++) {
            float cv[4], bv[4];
#pragma unroll
            for (int a = 0; a < 4; a++) cv[a] = sC[ti + a][n];
#pragma unroll
            for (int b2 = 0; b2 < 4; b2++) bv[b2] = sB[tj + b2][n];
#pragma unroll
            for (int a = 0; a < 4; a++)
#pragma unroll
                for (int b2 = 0; b2 < 4; b2++) r[a][b2] = fmaf(cv[a], bv[b2], r[a][b2]);
        }
#pragma unroll
        for (int a = 0; a < 4; a++)
#pragma unroll
            for (int b2 = 0; b2 < 4; b2++) {
                int i = ti + a, j = tj + b2;
                sGL[i][j] = (j <= i) ? r[a][b2] * expf(smn[i] - scum[j]) : 0.f;
            }
    }
    if (tid < 64) {
        float s = 0.f;
        for (int j = 0; j <= tid; j++) s += expf(smn[tid] - scum[j]);
        g_ndiag[abase + tid] = s;
    }
    __syncthreads();

    {
        float r[4][4];
#pragma unroll
        for (int a = 0; a < 4; a++)
#pragma unroll
            for (int b2 = 0; b2 < 4; b2++) r[a][b2] = 0.f;
        for (int j = 0; j < 64; j++) {
            float gl[4], xv[4];
#pragma unroll
            for (int a = 0; a < 4; a++) gl[a] = sGL[ti + a][j];
#pragma unroll
            for (int b2 = 0; b2 < 4; b2++) xv[b2] = sX[j][tj + b2];
#pragma unroll
            for (int a = 0; a < 4; a++)
#pragma unroll
                for (int b2 = 0; b2 < 4; b2++) r[a][b2] = fmaf(gl[a], xv[b2], r[a][b2]);
        }
#pragma unroll
        for (int a = 0; a < 4; a++)
#pragma unroll
            for (int b2 = 0; b2 < 4; b2++)
                g_Ydiag[base + (size_t)(ti + a) * 64 + (tj + b2)] = r[a][b2];
    }
    {
        float r[4][4];
#pragma unroll
        for (int a = 0; a < 4; a++)
#pragma unroll
            for (int b2 = 0; b2 < 4; b2++) r[a][b2] = 0.f;
        for (int l = 0; l < 64; l++) {
            float d = sds[l];
            float xv[4], bv[4];
#pragma unroll
            for (int a = 0; a < 4; a++) xv[a] = sX[l][ti + a] * d;
#pragma unroll
            for (int b2 = 0; b2 < 4; b2++) bv[b2] = sB[l][tj + b2];
#pragma unroll
            for (int a = 0; a < 4; a++)
#pragma unroll
                for (int b2 = 0; b2 < 4; b2++) r[a][b2] = fmaf(xv[a], bv[b2], r[a][b2]);
        }
        size_t sb = ((size_t)bh * NCH + c) * 4096;
#pragma unroll
        for (int a = 0; a < 4; a++)
#pragma unroll
            for (int b2 = 0; b2 < 4; b2++)
                g_states[sb + (size_t)(ti + a) * 64 + (tj + b2)] = r[a][b2];
    }
}

// --------------- chunk recurrence scan --------------------------------------------
__global__ void scan_k()
{
    int bh   = blockIdx.x >> 3;
    int part = blockIdx.x & 7;
    int tid  = threadIdx.x;
    int e0   = part * 512 + tid;
    size_t sb = (size_t)bh * NCH * 4096;

    float r0 = 0.f, r1 = 0.f;
    float minc = 0.f, cc = 0.f, nacc = 0.f;
    g_nstates[sb + e0] = 0.f;
    g_nstates[sb + e0 + 256] = 0.f;
    if (part == 0 && tid == 0) g_nnew[bh * NCH] = 0.f;
    for (int z = 0; z < 63; z++) {
        cc += g_Atot[bh * NCH + z];
        float m2 = fminf(minc, cc);
        float f = expf(m2 - minc);
        float g = expf(m2 - cc);
        r0 = r0 * f + g * g_states[sb + (size_t)z * 4096 + e0];
        r1 = r1 * f + g * g_states[sb + (size_t)z * 4096 + e0 + 256];
        minc = m2;
        g_nstates[sb + (size_t)(z + 1) * 4096 + e0] = r0;
        g_nstates[sb + (size_t)(z + 1) * 4096 + e0 + 256] = r1;
        if (part == 0 && tid == 0) {
            nacc = nacc * f + g * g_ndec[bh * NCH + z];
            g_nnew[bh * NCH + z + 1] = nacc;
        }
    }
}

// --------------- Y_off + combine + normalize + bf16 split -------------------------
__global__ __launch_bounds__(256) void yoff_k()
{
    __shared__ float sC[64][65];
    __shared__ float sS[64][65];
    __shared__ float scum[64];
    __shared__ float sdo[64];
    __shared__ float sMx;

    int bh = blockIdx.x >> 6;
    int c  = blockIdx.x & 63;
    int b  = bh >> 4;
    int h  = bh & 15;
    int tid = threadIdx.x;
    size_t baseC = ((size_t)bh * SEQL + (size_t)c * 64) * HD;
    size_t baseS = ((size_t)bh * NCH + c) * 4096;

    for (int i = tid; i < 4096; i += 256) {
        sC[i >> 6][i & 63] = g_Cm[baseC + i];
        sS[i >> 6][i & 63] = g_nstates[baseS + i];
    }
    if (tid < 64) scum[tid] = g_cumA[(size_t)bh * SEQL + c * 64 + tid];
    __syncthreads();
    if (tid == 0) {
        float mx = -1e30f;
        for (int l = 0; l < 64; l++) mx = fmaxf(mx, scum[l]);
        sMx = mx;
    }
    __syncthreads();
    if (tid < 64) sdo[tid] = expf(scum[tid] - sMx);
    __syncthreads();

    float nn = g_nnew[bh * NCH + c];
    int tl = (tid >> 4) * 4;
    int tp = (tid & 15) * 4;
    float r[4][4];
#pragma unroll
    for (int a = 0; a < 4; a++)
#pragma unroll
        for (int b2 = 0; b2 < 4; b2++) r[a][b2] = 0.f;
    for (int n = 0; n < 64; n++) {
        float cv[4], sv[4];
#pragma unroll
        for (int a = 0; a < 4; a++) cv[a] = sC[tl + a][n];
#pragma unroll
        for (int b2 = 0; b2 < 4; b2++) sv[b2] = sS[tp + b2][n];
#pragma unroll
        for (int a = 0; a < 4; a++)
#pragma unroll
            for (int b2 = 0; b2 < 4; b2++) r[a][b2] = fmaf(cv[a], sv[b2], r[a][b2]);
    }
#pragma unroll
    for (int a = 0; a < 4; a++) {
        int l = tl + a;
        float d = sdo[l];
        float nm = g_ndiag[(size_t)bh * SEQL + c * 64 + l] + nn * d;
        int s = c * 64 + l;
        size_t rowb = ((size_t)b * SEQL + s) * K3 + h * 64;
#pragma unroll
        for (int b2 = 0; b2 < 4; b2++) {
            int p = tp + b2;
            float y = g_Ydiag[baseC + (size_t)l * 64 + p] + d * r[a][b2];
            float val = y / nm;
            __nv_bfloat16 hi = __float2bfloat16(val);
            __nv_bfloat16 lo = __float2bfloat16(val - __bfloat162float(hi));
            g_ys[rowb + p]            = hi;
            g_ys[rowb + p + DMODEL]   = hi;
            g_ys[rowb + p + 2*DMODEL] = lo;
        }
    }
}

// ------------------------------- launch ---------------------------------------------
extern "C" void kernel_launch(void* const* d_in, const int* in_sizes, int n_in,
                              void* d_out, int out_size)
{
    const float* x   = (const float*)d_in[0];
    const float* ipw = (const float*)d_in[1];
    const float* cw  = (const float*)d_in[2];
    const float* cb  = (const float*)d_in[3];
    const float* wb  = (const float*)d_in[4];
    const float* opw = (const float*)d_in[5];
    float* out = (float*)d_out;

    float *p_xw = nullptr;
    __nv_bfloat16 *p_xs, *p_ws, *p_w2s, *p_ys;
    cudaGetSymbolAddress((void**)&p_xw, g_xw);
    cudaGetSymbolAddress((void**)&p_xs, g_xs);
    cudaGetSymbolAddress((void**)&p_ws, g_ws);
    cudaGetSymbolAddress((void**)&p_w2s, g_w2s);
    cudaGetSymbolAddress((void**)&p_ys, g_ys);

    const int SMEM_CHUNK = 4 * 64 * 65 * 4;
    cudaFuncSetAttribute(chunk_k, cudaFuncAttributeMaxDynamicSharedMemorySize, SMEM_CHUNK);
    const int SMEM_GEMM = NSTG * (int)STGB;
    cudaFuncSetAttribute(mma_gemm_k, cudaFuncAttributeMaxDynamicSharedMemorySize, SMEM_GEMM);

    // 0) bf16 splits
    split_k<<<(BSN * DMODEL + 255) / 256, 256>>>(x, p_xs, BSN, DMODEL, BSN, 0);
    split_k<<<(NPAD_IP * DMODEL + 255) / 256, 256>>>(ipw, p_ws, DINP, DMODEL, NPAD_IP, 1);
    split_k<<<(DMODEL * DMODEL + 255) / 256, 256>>>(opw, p_w2s, DMODEL, DMODEL, DMODEL, 1);

    // 1) in_proj via HMMA
    {
        dim3 g(NPAD_IP / 128, BSN / 128);
        mma_gemm_k<<<g, 256, SMEM_GEMM>>>(p_xs, p_ws, p_xw, K3, DINP, DINP);
    }

    // 2) conv + split
    conv_split_k<<<(BSN * CONVD + 255) / 256, 256>>>(cw, cb);

    // 3) A scale
    a_scale_k<<<(BSN * NH + 255) / 256, 256>>>(wb);

    // 4) per-chunk tiles
    chunk_k<<<BHN * NCH, 256, SMEM_CHUNK>>>();

    // 5) chunk recurrence scan
    scan_k<<<BHN * 8, 256>>>();

    // 6) off-diagonal + normalize + fused bf16 split
    yoff_k<<<BHN * NCH, 256>>>();

    // 7) out_proj via HMMA
    {
        dim3 g(DMODEL / 128, BSN / 128);
        mma_gemm_k<<<g, 256, SMEM_GEMM>>>(p_ys, p_w2s, out, K3, DMODEL, DMODEL);
    }
}

// round 6
// speedup vs baseline: 2.1320x; 1.0915x over previous
#include <cuda_runtime.h>
#include <cuda_bf16.h>
#include <math.h>
#include <stdint.h>

#define BATCHN 2
#define SEQL   4096
#define DMODEL 1024
#define NH     16
#define HD     64
#define CHUNKL 64
#define NCH    64
#define CONVD  3072
#define DINP   3088
#define BHN    (BATCHN*NH)
#define BSN    (BATCHN*SEQL)
#define K3     3072
#define NPAD_IP 3200

// ---------------- scratch ------------------------------------------------------
__device__ float g_xw[(size_t)BSN*DINP];
__device__ float g_Cm[(size_t)BHN*SEQL*HD];
__device__ float g_Bm[(size_t)BHN*SEQL*HD];
__device__ float g_Xv[(size_t)BHN*SEQL*HD];
__device__ float g_Av[(size_t)BHN*SEQL];
__device__ float g_cumA[(size_t)BHN*SEQL];
__device__ float g_states[(size_t)BHN*NCH*HD*HD];
__device__ float g_nstates[(size_t)BHN*NCH*HD*HD];
__device__ float g_Atot[BHN*NCH];
__device__ float g_ndec[BHN*NCH];
__device__ float g_nnew[BHN*NCH];
__device__ float g_Ydiag[(size_t)BHN*SEQL*HD];
__device__ float g_ndiag[(size_t)BHN*SEQL];
__device__ __nv_bfloat16 g_xs[(size_t)BSN*K3];
__device__ __nv_bfloat16 g_ws[(size_t)NPAD_IP*K3];
__device__ __nv_bfloat16 g_w2s[(size_t)DMODEL*K3];
__device__ __nv_bfloat16 g_ys[(size_t)BSN*K3];

// ---------------- helpers ------------------------------------------------------
__device__ __forceinline__ uint32_t smem_u32(const void* p) {
    uint32_t a;
    asm("{ .reg .u64 t; cvta.to.shared.u64 t, %1; cvt.u32.u64 %0, t; }" : "=r"(a) : "l"(p));
    return a;
}
#define CP16(dst, src)  asm volatile("cp.async.cg.shared.global [%0], [%1], 16;" :: "r"(dst), "l"(src) : "memory")
#define CP_COMMIT()     asm volatile("cp.async.commit_group;" ::: "memory")

__device__ __forceinline__ void ldm_x4(uint32_t* r, uint32_t addr) {
    asm volatile("ldmatrix.sync.aligned.m8n8.x4.shared.b16 {%0,%1,%2,%3}, [%4];"
        : "=r"(r[0]), "=r"(r[1]), "=r"(r[2]), "=r"(r[3]) : "r"(addr));
}
__device__ __forceinline__ void mma_bf16(float* c, const uint32_t* a, const uint32_t* b) {
    asm volatile("mma.sync.aligned.m16n8k16.row.col.f32.bf16.bf16.f32 "
        "{%0,%1,%2,%3},{%4,%5,%6,%7},{%8,%9},{%0,%1,%2,%3};"
        : "+f"(c[0]), "+f"(c[1]), "+f"(c[2]), "+f"(c[3])
        : "r"(a[0]), "r"(a[1]), "r"(a[2]), "r"(a[3]), "r"(b[0]), "r"(b[1]));
}

// ---------------- bf16 HMMA GEMM ------------------------------------------------
// BK=64 per barrier, 3 stages, 2 CTAs/SM.
#define BK    64
#define ROWE  72                        // 64 data + 8 pad elems (144B pitch)
#define NSTG  3
#define STGB  (2u * 128 * ROWE * 2)     // 36864 B
#define OPB   (128u * ROWE * 2)         // 18432 B

__global__ __launch_bounds__(256, 2) void mma_gemm_k(
    const __nv_bfloat16* __restrict__ A, const __nv_bfloat16* __restrict__ B,
    float* __restrict__ C, int K, int Nout, int ldc)
{
    extern __shared__ __align__(16) __nv_bfloat16 dsm[];

    const int tid  = threadIdx.x;
    const int lane = tid & 31;
    const int wid  = tid >> 5;
    const int wm   = wid & 1;
    const int wn   = wid >> 1;
    const int bm   = blockIdx.y * 128;
    const int bn   = blockIdx.x * 128;
    const int nk   = K / BK;

    float acc[4][4][4];
#pragma unroll
    for (int i = 0; i < 4; i++)
#pragma unroll
        for (int j = 0; j < 4; j++)
#pragma unroll
            for (int e = 0; e < 4; e++) acc[i][j][e] = 0.f;

    const int r0 = tid >> 3;            // 0..31
    const int c0 = (tid & 7) * 8;       // element offset in row (0..56)
    uint32_t sbase = smem_u32(dsm);

    uint32_t aoff[4];
#pragma unroll
    for (int mi = 0; mi < 4; mi++) {
        int row = wm * 64 + mi * 16 + (lane & 15);
        aoff[mi] = (uint32_t)(row * ROWE + (lane >> 4) * 8) * 2;
    }
    uint32_t boffp[2];
#pragma unroll
    for (int pi = 0; pi < 2; pi++) {
        int l2  = lane & 15;
        int grp = lane >> 4;
        int row = wn * 32 + (pi * 2 + grp) * 8 + (l2 & 7);
        boffp[pi] = (uint32_t)(row * ROWE + ((l2 >> 3) & 1) * 8) * 2;
    }

    // prologue: stages 0,1
#pragma unroll
    for (int j = 0; j < 2; j++) {
        uint32_t sa = sbase + j * STGB, sb = sa + OPB;
        int k0 = j * BK;
#pragma unroll
        for (int i = 0; i < 4; i++) {
            int r = r0 + i * 32;
            CP16(sa + (uint32_t)(r * ROWE + c0) * 2, A + (size_t)(bm + r) * K + k0 + c0);
            CP16(sb + (uint32_t)(r * ROWE + c0) * 2, B + (size_t)(bn + r) * K + k0 + c0);
        }
        CP_COMMIT();
    }

    int st = 0;  // stage index for kt
#pragma unroll 1
    for (int kt = 0; kt < nk; kt++) {
        asm volatile("cp.async.wait_group 1;" ::: "memory");
        __syncthreads();

        int jn = kt + 2;
        if (jn < nk) {
            int st2 = st + 2; if (st2 >= 3) st2 -= 3;
            uint32_t sa = sbase + (uint32_t)st2 * STGB, sb = sa + OPB;
            int k0 = jn * BK;
#pragma unroll
            for (int i = 0; i < 4; i++) {
                int r = r0 + i * 32;
                CP16(sa + (uint32_t)(r * ROWE + c0) * 2, A + (size_t)(bm + r) * K + k0 + c0);
                CP16(sb + (uint32_t)(r * ROWE + c0) * 2, B + (size_t)(bn + r) * K + k0 + c0);
            }
        }
        CP_COMMIT();

        uint32_t sa = sbase + (uint32_t)st * STGB, sb = sa + OPB;

#pragma unroll
        for (int ksp = 0; ksp < 2; ksp++) {
            // batch fragments for ks = 2*ksp, 2*ksp+1
            uint32_t a[2][4][4];
            uint32_t bp[2][2][4];
#pragma unroll
            for (int k2 = 0; k2 < 2; k2++) {
                uint32_t kadd = (uint32_t)((ksp * 2 + k2) * 16) * 2;
#pragma unroll
                for (int mi = 0; mi < 4; mi++) ldm_x4(a[k2][mi], sa + aoff[mi] + kadd);
#pragma unroll
                for (int pi = 0; pi < 2; pi++) ldm_x4(bp[k2][pi], sb + boffp[pi] + kadd);
            }
#pragma unroll
            for (int k2 = 0; k2 < 2; k2++)
#pragma unroll
                for (int mi = 0; mi < 4; mi++)
#pragma unroll
                    for (int ni = 0; ni < 4; ni++)
                        mma_bf16(acc[mi][ni], a[k2][mi], &bp[k2][ni >> 1][(ni & 1) * 2]);
        }
        if (++st == 3) st = 0;
    }

    // epilogue
#pragma unroll
    for (int mi = 0; mi < 4; mi++) {
        int row = bm + wm * 64 + mi * 16 + (lane >> 2);
#pragma unroll
        for (int ni = 0; ni < 4; ni++) {
            int col = bn + wn * 32 + ni * 8 + (lane & 3) * 2;
            if (col < Nout) {
                *(float2*)(C + (size_t)row * ldc + col)       = make_float2(acc[mi][ni][0], acc[mi][ni][1]);
                *(float2*)(C + (size_t)(row + 8) * ldc + col) = make_float2(acc[mi][ni][2], acc[mi][ni][3]);
            }
        }
    }
}

// ---------------- fp32 -> bf16 hi/lo split --------------------------------------
__global__ void split_k(const float* __restrict__ src, __nv_bfloat16* __restrict__ dst,
                        int rows, int Kin, int rowsPad, int mode)
{
    int gi = blockIdx.x * blockDim.x + threadIdx.x;
    if (gi >= rowsPad * Kin) return;
    int r = gi / Kin, k = gi % Kin;
    float v = (r < rows) ? src[(size_t)r * Kin + k] : 0.f;
    __nv_bfloat16 hi = __float2bfloat16(v);
    __nv_bfloat16 lo = __float2bfloat16(v - __bfloat162float(hi));
    size_t b = (size_t)r * (3 * Kin) + k;
    dst[b] = hi;
    dst[b + Kin]     = mode ? lo : hi;
    dst[b + 2 * Kin] = mode ? hi : lo;
}

// --------------- depthwise causal conv + split ----------------------------------
__global__ void conv_split_k(const float* __restrict__ cw, const float* __restrict__ cb)
{
    int gi = blockIdx.x * blockDim.x + threadIdx.x;
    if (gi >= BSN * CONVD) return;
    int ch = gi % CONVD;
    int bs = gi / CONVD;
    int s  = bs % SEQL;
    int b  = bs / SEQL;
    float acc = cb[ch];
#pragma unroll
    for (int k = 0; k < 4; k++) {
        int ss = s - 3 + k;
        if (ss >= 0)
            acc = fmaf(g_xw[(size_t)(b * SEQL + ss) * DINP + ch], cw[ch * 4 + k], acc);
    }
    int sect = ch >> 10;
    int h = (ch & 1023) >> 6;
    int n = ch & 63;
    float* dst = (sect == 0) ? g_Cm : (sect == 1) ? g_Bm : g_Xv;
    dst[((size_t)(b * NH + h) * SEQL + s) * HD + n] = acc;
}

__global__ void a_scale_k(const float* __restrict__ w_base)
{
    int gi = blockIdx.x * blockDim.x + threadIdx.x;
    if (gi >= BSN * NH) return;
    int h  = gi % NH;
    int bs = gi / NH;
    int s  = bs % SEQL;
    int b  = bs / SEQL;
    g_Av[((size_t)(b * NH + h)) * SEQL + s] = g_xw[(size_t)bs * DINP + CONVD + h] * w_base[h];
}

// --------------- per-chunk tile kernel -------------------------------------------
__global__ __launch_bounds__(256) void chunk_k()
{
    extern __shared__ float sh[];
    float (*sC)[65]  = (float(*)[65])sh;
    float (*sB)[65]  = (float(*)[65])(sh + 64 * 65);
    float (*sX)[65]  = (float(*)[65])(sh + 2 * 64 * 65);
    float (*sGL)[65] = (float(*)[65])(sh + 3 * 64 * 65);
    __shared__ float scum[64];
    __shared__ float smn[64];
    __shared__ float sds[64];

    int bh = blockIdx.x >> 6;
    int c  = blockIdx.x & 63;
    int tid = threadIdx.x;
    size_t base = ((size_t)bh * SEQL + (size_t)c * CHUNKL) * HD;
    size_t abase = (size_t)bh * SEQL + c * 64;

    for (int i = tid; i < 64 * 64; i += 256) {
        int l = i >> 6, n = i & 63;
        sC[l][n] = g_Cm[base + i];
        sB[l][n] = g_Bm[base + i];
        sX[l][n] = g_Xv[base + i];
    }
    if (tid < 32) {
        float v0 = g_Av[abase + 2 * tid];
        float v1 = g_Av[abase + 2 * tid + 1];
        float s = v0 + v1;
#pragma unroll
        for (int o = 1; o < 32; o <<= 1) {
            float t = __shfl_up_sync(0xffffffffu, s, o);
            if (tid >= o) s += t;
        }
        float c1 = s, cc0 = s - v1;
        scum[2 * tid] = cc0; scum[2 * tid + 1] = c1;
        g_cumA[abase + 2 * tid] = cc0;
        g_cumA[abase + 2 * tid + 1] = c1;
        float mm = fminf(cc0, c1);
#pragma unroll
        for (int o = 1; o < 32; o <<= 1) {
            float t = __shfl_up_sync(0xffffffffu, mm, o);
            if (tid >= o) mm = fminf(mm, t);
        }
        float prev = __shfl_up_sync(0xffffffffu, mm, 1);
        if (tid == 0) prev = 1e30f;
        smn[2 * tid]     = fminf(prev, cc0);
        smn[2 * tid + 1] = fminf(prev, fminf(cc0, c1));
        float mtot = __shfl_sync(0xffffffffu, mm, 31);
        float d0 = expf(mtot - cc0), d1 = expf(mtot - c1);
        sds[2 * tid] = d0; sds[2 * tid + 1] = d1;
        float nd = d0 + d1;
#pragma unroll
        for (int o = 16; o; o >>= 1) nd += __shfl_xor_sync(0xffffffffu, nd, o);
        float ctot = __shfl_sync(0xffffffffu, c1, 31);
        if (tid == 0) { g_Atot[bh * NCH + c] = ctot; g_ndec[bh * NCH + c] = nd; }
    }
    __syncthreads();

    int tj = (tid & 15) * 4;
    int ti = (tid >> 4) * 4;

    {
        float r[4][4];
#pragma unroll
        for (int a = 0; a < 4; a++)
#pragma unroll
            for (int b2 = 0; b2 < 4; b2++) r[a][b2] = 0.f;
        for (int n = 0; n < 64; n++) {
            float cv[4], bv[4];
#pragma unroll
            for (int a = 0; a < 4; a++) cv[a] = sC[ti + a][n];
#pragma unroll
            for (int b2 = 0; b2 < 4; b2++) bv[b2] = sB[tj + b2][n];
#pragma unroll
            for (int a = 0; a < 4; a++)
#pragma unroll
                for (int b2 = 0; b2 < 4; b2++) r[a][b2] = fmaf(cv[a], bv[b2], r[a][b2]);
        }
#pragma unroll
        for (int a = 0; a < 4; a++)
#pragma unroll
            for (int b2 = 0; b2 < 4; b2++) {
                int i = ti + a, j = tj + b2;
                sGL[i][j] = (j <= i) ? r[a][b2] * expf(smn[i] - scum[j]) : 0.f;
            }
    }
    if (tid < 64) {
        float s = 0.f;
        for (int j = 0; j <= tid; j++) s += expf(smn[tid] - scum[j]);
        g_ndiag[abase + tid] = s;
    }
    __syncthreads();

    {
        float r[4][4];
#pragma unroll
        for (int a = 0; a < 4; a++)
#pragma unroll
            for (int b2 = 0; b2 < 4; b2++) r[a][b2] = 0.f;
        for (int j = 0; j < 64; j++) {
            float gl[4], xv[4];
#pragma unroll
            for (int a = 0; a < 4; a++) gl[a] = sGL[ti + a][j];
#pragma unroll
            for (int b2 = 0; b2 < 4; b2++) xv[b2] = sX[j][tj + b2];
#pragma unroll
            for (int a = 0; a < 4; a++)
#pragma unroll
                for (int b2 = 0; b2 < 4; b2++) r[a][b2] = fmaf(gl[a], xv[b2], r[a][b2]);
        }
#pragma unroll
        for (int a = 0; a < 4; a++)
#pragma unroll
            for (int b2 = 0; b2 < 4; b2++)
                g_Ydiag[base + (size_t)(ti + a) * 64 + (tj + b2)] = r[a][b2];
    }
    {
        float r[4][4];
#pragma unroll
        for (int a = 0; a < 4; a++)
#pragma unroll
            for (int b2 = 0; b2 < 4; b2++) r[a][b2] = 0.f;
        for (int l = 0; l < 64; l++) {
            float d = sds[l];
            float xv[4], bv[4];
#pragma unroll
            for (int a = 0; a < 4; a++) xv[a] = sX[l][ti + a] * d;
#pragma unroll
            for (int b2 = 0; b2 < 4; b2++) bv[b2] = sB[l][tj + b2];
#pragma unroll
            for (int a = 0; a < 4; a++)
#pragma unroll
                for (int b2 = 0; b2 < 4; b2++) r[a][b2] = fmaf(xv[a], bv[b2], r[a][b2]);
        }
        size_t sb = ((size_t)bh * NCH + c) * 4096;
#pragma unroll
        for (int a = 0; a < 4; a++)
#pragma unroll
            for (int b2 = 0; b2 < 4; b2++)
                g_states[sb + (size_t)(ti + a) * 64 + (tj + b2)] = r[a][b2];
    }
}

// --------------- chunk recurrence scan --------------------------------------------
__global__ void scan_k()
{
    int bh   = blockIdx.x >> 3;
    int part = blockIdx.x & 7;
    int tid  = threadIdx.x;
    int e0   = part * 512 + tid;
    size_t sb = (size_t)bh * NCH * 4096;

    float r0 = 0.f, r1 = 0.f;
    float minc = 0.f, cc = 0.f, nacc = 0.f;
    g_nstates[sb + e0] = 0.f;
    g_nstates[sb + e0 + 256] = 0.f;
    if (part == 0 && tid == 0) g_nnew[bh * NCH] = 0.f;
    for (int z = 0; z < 63; z++) {
        cc += g_Atot[bh * NCH + z];
        float m2 = fminf(minc, cc);
        float f = expf(m2 - minc);
        float g = expf(m2 - cc);
        r0 = r0 * f + g * g_states[sb + (size_t)z * 4096 + e0];
        r1 = r1 * f + g * g_states[sb + (size_t)z * 4096 + e0 + 256];
        minc = m2;
        g_nstates[sb + (size_t)(z + 1) * 4096 + e0] = r0;
        g_nstates[sb + (size_t)(z + 1) * 4096 + e0 + 256] = r1;
        if (part == 0 && tid == 0) {
            nacc = nacc * f + g * g_ndec[bh * NCH + z];
            g_nnew[bh * NCH + z + 1] = nacc;
        }
    }
}

// --------------- Y_off + combine + normalize + bf16 split -------------------------
__global__ __launch_bounds__(256) void yoff_k()
{
    __shared__ float sC[64][65];
    __shared__ float sS[64][65];
    __shared__ float scum[64];
    __shared__ float sdo[64];
    __shared__ float sMx;

    int bh = blockIdx.x >> 6;
    int c  = blockIdx.x & 63;
    int b  = bh >> 4;
    int h  = bh & 15;
    int tid = threadIdx.x;
    size_t baseC = ((size_t)bh * SEQL + (size_t)c * 64) * HD;
    size_t baseS = ((size_t)bh * NCH + c) * 4096;

    for (int i = tid; i < 4096; i += 256) {
        sC[i >> 6][i & 63] = g_Cm[baseC + i];
        sS[i >> 6][i & 63] = g_nstates[baseS + i];
    }
    if (tid < 64) scum[tid] = g_cumA[(size_t)bh * SEQL + c * 64 + tid];
    __syncthreads();
    if (tid == 0) {
        float mx = -1e30f;
        for (int l = 0; l < 64; l++) mx = fmaxf(mx, scum[l]);
        sMx = mx;
    }
    __syncthreads();
    if (tid < 64) sdo[tid] = expf(scum[tid] - sMx);
    __syncthreads();

    float nn = g_nnew[bh * NCH + c];
    int tl = (tid >> 4) * 4;
    int tp = (tid & 15) * 4;
    float r[4][4];
#pragma unroll
    for (int a = 0; a < 4; a++)
#pragma unroll
        for (int b2 = 0; b2 < 4; b2++) r[a][b2] = 0.f;
    for (int n = 0; n < 64; n++) {
        float cv[4], sv[4];
#pragma unroll
        for (int a = 0; a < 4; a++) cv[a] = sC[tl + a][n];
#pragma unroll
        for (int b2 = 0; b2 < 4; b2++) sv[b2] = sS[tp + b2][n];
#pragma unroll
        for (int a = 0; a < 4; a++)
#pragma unroll
            for (int b2 = 0; b2 < 4; b2++) r[a][b2] = fmaf(cv[a], sv[b2], r[a][b2]);
    }
#pragma unroll
    for (int a = 0; a < 4; a++) {
        int l = tl + a;
        float d = sdo[l];
        float nm = g_ndiag[(size_t)bh * SEQL + c * 64 + l] + nn * d;
        int s = c * 64 + l;
        size_t rowb = ((size_t)b * SEQL + s) * K3 + h * 64;
#pragma unroll
        for (int b2 = 0; b2 < 4; b2++) {
            int p = tp + b2;
            float y = g_Ydiag[baseC + (size_t)l * 64 + p] + d * r[a][b2];
            float val = y / nm;
            __nv_bfloat16 hi = __float2bfloat16(val);
            __nv_bfloat16 lo = __float2bfloat16(val - __bfloat162float(hi));
            g_ys[rowb + p]            = hi;
            g_ys[rowb + p + DMODEL]   = hi;
            g_ys[rowb + p + 2*DMODEL] = lo;
        }
    }
}

// ------------------------------- launch ---------------------------------------------
extern "C" void kernel_launch(void* const* d_in, const int* in_sizes, int n_in,
                              void* d_out, int out_size)
{
    const float* x   = (const float*)d_in[0];
    const float* ipw = (const float*)d_in[1];
    const float* cw  = (const float*)d_in[2];
    const float* cb  = (const float*)d_in[3];
    const float* wb  = (const float*)d_in[4];
    const float* opw = (const float*)d_in[5];
    float* out = (float*)d_out;

    float *p_xw = nullptr;
    __nv_bfloat16 *p_xs, *p_ws, *p_w2s, *p_ys;
    cudaGetSymbolAddress((void**)&p_xw, g_xw);
    cudaGetSymbolAddress((void**)&p_xs, g_xs);
    cudaGetSymbolAddress((void**)&p_ws, g_ws);
    cudaGetSymbolAddress((void**)&p_w2s, g_w2s);
    cudaGetSymbolAddress((void**)&p_ys, g_ys);

    const int SMEM_CHUNK = 4 * 64 * 65 * 4;
    cudaFuncSetAttribute(chunk_k, cudaFuncAttributeMaxDynamicSharedMemorySize, SMEM_CHUNK);
    const int SMEM_GEMM = NSTG * (int)STGB;   // 110592
    cudaFuncSetAttribute(mma_gemm_k, cudaFuncAttributeMaxDynamicSharedMemorySize, SMEM_GEMM);

    // 0) bf16 splits
    split_k<<<(BSN * DMODEL + 255) / 256, 256>>>(x, p_xs, BSN, DMODEL, BSN, 0);
    split_k<<<(NPAD_IP * DMODEL + 255) / 256, 256>>>(ipw, p_ws, DINP, DMODEL, NPAD_IP, 1);
    split_k<<<(DMODEL * DMODEL + 255) / 256, 256>>>(opw, p_w2s, DMODEL, DMODEL, DMODEL, 1);

    // 1) in_proj via HMMA
    {
        dim3 g(NPAD_IP / 128, BSN / 128);
        mma_gemm_k<<<g, 256, SMEM_GEMM>>>(p_xs, p_ws, p_xw, K3, DINP, DINP);
    }

    // 2) conv + split
    conv_split_k<<<(BSN * CONVD + 255) / 256, 256>>>(cw, cb);

    // 3) A scale
    a_scale_k<<<(BSN * NH + 255) / 256, 256>>>(wb);

    // 4) per-chunk tiles
    chunk_k<<<BHN * NCH, 256, SMEM_CHUNK>>>();

    // 5) chunk recurrence scan
    scan_k<<<BHN * 8, 256>>>();

    // 6) off-diagonal + normalize + fused bf16 split
    yoff_k<<<BHN * NCH, 256>>>();

    // 7) out_proj via HMMA
    {
        dim3 g(DMODEL / 128, BSN / 128);
        mma_gemm_k<<<g, 256, SMEM_GEMM>>>(p_ys, p_w2s, out, K3, DMODEL, DMODEL);
    }
}

// round 7
// speedup vs baseline: 2.3579x; 1.1059x over previous
#include <cuda_runtime.h>
#include <cuda_bf16.h>
#include <math.h>
#include <stdint.h>

#define BATCHN 2
#define SEQL   4096
#define DMODEL 1024
#define NH     16
#define HD     64
#define CHUNKL 64
#define NCH    64
#define CONVD  3072
#define DINP   3088
#define BHN    (BATCHN*NH)
#define BSN    (BATCHN*SEQL)
#define K3     3072
#define NPAD_IP 3200

// ---------------- scratch ------------------------------------------------------
__device__ float g_xw[(size_t)BSN*DINP];
__device__ float g_Cm[(size_t)BHN*SEQL*HD];
__device__ float g_Bm[(size_t)BHN*SEQL*HD];
__device__ float g_Xv[(size_t)BHN*SEQL*HD];
__device__ float g_cumA[(size_t)BHN*SEQL];
__device__ float g_states[(size_t)BHN*NCH*HD*HD];
__device__ float g_nstates[(size_t)BHN*NCH*HD*HD];
__device__ float g_Atot[BHN*NCH];
__device__ float g_ndec[BHN*NCH];
__device__ float g_nnew[BHN*NCH];
__device__ float g_Ydiag[(size_t)BHN*SEQL*HD];
__device__ float g_ndiag[(size_t)BHN*SEQL];
__device__ __nv_bfloat16 g_xs[(size_t)BSN*K3];
__device__ __nv_bfloat16 g_ws[(size_t)NPAD_IP*K3];
__device__ __nv_bfloat16 g_w2s[(size_t)DMODEL*K3];
__device__ __nv_bfloat16 g_ys[(size_t)BSN*K3];

// ---------------- helpers ------------------------------------------------------
__device__ __forceinline__ uint32_t smem_u32(const void* p) {
    uint32_t a;
    asm("{ .reg .u64 t; cvta.to.shared.u64 t, %1; cvt.u32.u64 %0, t; }" : "=r"(a) : "l"(p));
    return a;
}
#define CP16(dst, src)  asm volatile("cp.async.cg.shared.global [%0], [%1], 16;" :: "r"(dst), "l"(src) : "memory")
#define CP_COMMIT()     asm volatile("cp.async.commit_group;" ::: "memory")

__device__ __forceinline__ void ldm_x4(uint32_t* r, uint32_t addr) {
    asm volatile("ldmatrix.sync.aligned.m8n8.x4.shared.b16 {%0,%1,%2,%3}, [%4];"
        : "=r"(r[0]), "=r"(r[1]), "=r"(r[2]), "=r"(r[3]) : "r"(addr));
}
__device__ __forceinline__ void mma_bf16(float* c, const uint32_t* a, const uint32_t* b) {
    asm volatile("mma.sync.aligned.m16n8k16.row.col.f32.bf16.bf16.f32 "
        "{%0,%1,%2,%3},{%4,%5,%6,%7},{%8,%9},{%0,%1,%2,%3};"
        : "+f"(c[0]), "+f"(c[1]), "+f"(c[2]), "+f"(c[3])
        : "r"(a[0]), "r"(a[1]), "r"(a[2]), "r"(a[3]), "r"(b[0]), "r"(b[1]));
}

// ---------------- bf16 HMMA GEMM (BK=64, 3 stages) ------------------------------
#define BK    64
#define ROWE  72
#define NSTG  3
#define STGB  (2u * 128 * ROWE * 2)
#define OPB   (128u * ROWE * 2)

__global__ __launch_bounds__(256, 2) void mma_gemm_k(
    const __nv_bfloat16* __restrict__ A, const __nv_bfloat16* __restrict__ B,
    float* __restrict__ C, int K, int Nout, int ldc)
{
    extern __shared__ __align__(16) __nv_bfloat16 dsm[];

    const int tid  = threadIdx.x;
    const int lane = tid & 31;
    const int wid  = tid >> 5;
    const int wm   = wid & 1;
    const int wn   = wid >> 1;
    const int bm   = blockIdx.y * 128;
    const int bn   = blockIdx.x * 128;
    const int nk   = K / BK;

    float acc[4][4][4];
#pragma unroll
    for (int i = 0; i < 4; i++)
#pragma unroll
        for (int j = 0; j < 4; j++)
#pragma unroll
            for (int e = 0; e < 4; e++) acc[i][j][e] = 0.f;

    const int r0 = tid >> 3;
    const int c0 = (tid & 7) * 8;
    uint32_t sbase = smem_u32(dsm);

    uint32_t aoff[4];
#pragma unroll
    for (int mi = 0; mi < 4; mi++) {
        int row = wm * 64 + mi * 16 + (lane & 15);
        aoff[mi] = (uint32_t)(row * ROWE + (lane >> 4) * 8) * 2;
    }
    uint32_t boffp[2];
#pragma unroll
    for (int pi = 0; pi < 2; pi++) {
        int l2  = lane & 15;
        int grp = lane >> 4;
        int row = wn * 32 + (pi * 2 + grp) * 8 + (l2 & 7);
        boffp[pi] = (uint32_t)(row * ROWE + ((l2 >> 3) & 1) * 8) * 2;
    }

#pragma unroll
    for (int j = 0; j < 2; j++) {
        uint32_t sa = sbase + j * STGB, sb = sa + OPB;
        int k0 = j * BK;
#pragma unroll
        for (int i = 0; i < 4; i++) {
            int r = r0 + i * 32;
            CP16(sa + (uint32_t)(r * ROWE + c0) * 2, A + (size_t)(bm + r) * K + k0 + c0);
            CP16(sb + (uint32_t)(r * ROWE + c0) * 2, B + (size_t)(bn + r) * K + k0 + c0);
        }
        CP_COMMIT();
    }

    int st = 0;
#pragma unroll 1
    for (int kt = 0; kt < nk; kt++) {
        asm volatile("cp.async.wait_group 1;" ::: "memory");
        __syncthreads();

        int jn = kt + 2;
        if (jn < nk) {
            int st2 = st + 2; if (st2 >= 3) st2 -= 3;
            uint32_t sa = sbase + (uint32_t)st2 * STGB, sb = sa + OPB;
            int k0 = jn * BK;
#pragma unroll
            for (int i = 0; i < 4; i++) {
                int r = r0 + i * 32;
                CP16(sa + (uint32_t)(r * ROWE + c0) * 2, A + (size_t)(bm + r) * K + k0 + c0);
                CP16(sb + (uint32_t)(r * ROWE + c0) * 2, B + (size_t)(bn + r) * K + k0 + c0);
            }
        }
        CP_COMMIT();

        uint32_t sa = sbase + (uint32_t)st * STGB, sb = sa + OPB;

#pragma unroll
        for (int ksp = 0; ksp < 2; ksp++) {
            uint32_t a[2][4][4];
            uint32_t bp[2][2][4];
#pragma unroll
            for (int k2 = 0; k2 < 2; k2++) {
                uint32_t kadd = (uint32_t)((ksp * 2 + k2) * 16) * 2;
#pragma unroll
                for (int mi = 0; mi < 4; mi++) ldm_x4(a[k2][mi], sa + aoff[mi] + kadd);
#pragma unroll
                for (int pi = 0; pi < 2; pi++) ldm_x4(bp[k2][pi], sb + boffp[pi] + kadd);
            }
#pragma unroll
            for (int k2 = 0; k2 < 2; k2++)
#pragma unroll
                for (int mi = 0; mi < 4; mi++)
#pragma unroll
                    for (int ni = 0; ni < 4; ni++)
                        mma_bf16(acc[mi][ni], a[k2][mi], &bp[k2][ni >> 1][(ni & 1) * 2]);
        }
        if (++st == 3) st = 0;
    }

#pragma unroll
    for (int mi = 0; mi < 4; mi++) {
        int row = bm + wm * 64 + mi * 16 + (lane >> 2);
#pragma unroll
        for (int ni = 0; ni < 4; ni++) {
            int col = bn + wn * 32 + ni * 8 + (lane & 3) * 2;
            if (col < Nout) {
                *(float2*)(C + (size_t)row * ldc + col)       = make_float2(acc[mi][ni][0], acc[mi][ni][1]);
                *(float2*)(C + (size_t)(row + 8) * ldc + col) = make_float2(acc[mi][ni][2], acc[mi][ni][3]);
            }
        }
    }
}

// ---------------- fp32 -> bf16 hi/lo split --------------------------------------
__global__ void split_k(const float* __restrict__ src, __nv_bfloat16* __restrict__ dst,
                        int rows, int Kin, int rowsPad, int mode)
{
    int gi = blockIdx.x * blockDim.x + threadIdx.x;
    if (gi >= rowsPad * Kin) return;
    int r = gi / Kin, k = gi % Kin;
    float v = (r < rows) ? src[(size_t)r * Kin + k] : 0.f;
    __nv_bfloat16 hi = __float2bfloat16(v);
    __nv_bfloat16 lo = __float2bfloat16(v - __bfloat162float(hi));
    size_t b = (size_t)r * (3 * Kin) + k;
    dst[b] = hi;
    dst[b + Kin]     = mode ? lo : hi;
    dst[b + 2 * Kin] = mode ? hi : lo;
}

// --------------- tiled depthwise causal conv + split ----------------------------
// grid (BSN/32, CONVD/256), block 256. smem tile [35][256].
__global__ __launch_bounds__(256) void conv_split_k(const float* __restrict__ cw,
                                                    const float* __restrict__ cb)
{
    __shared__ float tile[35][256];
    int bs_blk = blockIdx.x;
    int b = bs_blk >> 7;             // SEQL/32 = 128 blocks per batch
    int srow0 = (bs_blk & 127) * 32;
    int ch0 = blockIdx.y * 256;
    int tid = threadIdx.x;
    int ch = ch0 + tid;

    float w0 = cw[ch * 4 + 0], w1 = cw[ch * 4 + 1];
    float w2 = cw[ch * 4 + 2], w3 = cw[ch * 4 + 3];
    float bias = cb[ch];

#pragma unroll
    for (int i = 0; i < 35; i++) {
        int row = srow0 - 3 + i;
        tile[i][tid] = (row >= 0) ? g_xw[((size_t)(b * SEQL + row)) * DINP + ch] : 0.f;
    }
    __syncthreads();

    int sect = ch >> 10;
    int h = (ch & 1023) >> 6;
    int n = ch & 63;
    float* dst = (sect == 0) ? g_Cm : (sect == 1) ? g_Bm : g_Xv;
    size_t dbase = ((size_t)(b * NH + h) * SEQL) * HD + n;

#pragma unroll
    for (int j = 0; j < 32; j++) {
        float acc = fmaf(tile[j][tid], w0,
                    fmaf(tile[j + 1][tid], w1,
                    fmaf(tile[j + 2][tid], w2,
                    fmaf(tile[j + 3][tid], w3, bias))));
        dst[dbase + (size_t)(srow0 + j) * HD] = acc;
    }
}

// --------------- per-chunk tile kernel (A-scale fused) ----------------------------
__global__ __launch_bounds__(256) void chunk_k(const float* __restrict__ w_base)
{
    extern __shared__ float sh[];
    float (*sC)[65]  = (float(*)[65])sh;
    float (*sB)[65]  = (float(*)[65])(sh + 64 * 65);
    float (*sX)[65]  = (float(*)[65])(sh + 2 * 64 * 65);
    float (*sGL)[65] = (float(*)[65])(sh + 3 * 64 * 65);
    __shared__ float scum[64];
    __shared__ float smn[64];
    __shared__ float sds[64];

    int bh = blockIdx.x >> 6;
    int c  = blockIdx.x & 63;
    int b  = bh >> 4;
    int h  = bh & 15;
    int tid = threadIdx.x;
    size_t base = ((size_t)bh * SEQL + (size_t)c * CHUNKL) * HD;
    size_t abase = (size_t)bh * SEQL + c * 64;

    {
        const float4* pC = (const float4*)(g_Cm + base);
        const float4* pB = (const float4*)(g_Bm + base);
        const float4* pX = (const float4*)(g_Xv + base);
        for (int i4 = tid; i4 < 1024; i4 += 256) {
            int l = i4 >> 4, n = (i4 & 15) * 4;
            float4 v = pC[i4]; sC[l][n] = v.x; sC[l][n+1] = v.y; sC[l][n+2] = v.z; sC[l][n+3] = v.w;
            v = pB[i4]; sB[l][n] = v.x; sB[l][n+1] = v.y; sB[l][n+2] = v.z; sB[l][n+3] = v.w;
            v = pX[i4]; sX[l][n] = v.x; sX[l][n+1] = v.y; sX[l][n+2] = v.z; sX[l][n+3] = v.w;
        }
    }
    if (tid < 32) {
        float wbh = w_base[h];
        float v0 = g_xw[(size_t)(b * SEQL + c * 64 + 2 * tid)     * DINP + CONVD + h] * wbh;
        float v1 = g_xw[(size_t)(b * SEQL + c * 64 + 2 * tid + 1) * DINP + CONVD + h] * wbh;
        float s = v0 + v1;
#pragma unroll
        for (int o = 1; o < 32; o <<= 1) {
            float t = __shfl_up_sync(0xffffffffu, s, o);
            if (tid >= o) s += t;
        }
        float c1 = s, cc0 = s - v1;
        scum[2 * tid] = cc0; scum[2 * tid + 1] = c1;
        g_cumA[abase + 2 * tid] = cc0;
        g_cumA[abase + 2 * tid + 1] = c1;
        float mm = fminf(cc0, c1);
#pragma unroll
        for (int o = 1; o < 32; o <<= 1) {
            float t = __shfl_up_sync(0xffffffffu, mm, o);
            if (tid >= o) mm = fminf(mm, t);
        }
        float prev = __shfl_up_sync(0xffffffffu, mm, 1);
        if (tid == 0) prev = 1e30f;
        smn[2 * tid]     = fminf(prev, cc0);
        smn[2 * tid + 1] = fminf(prev, fminf(cc0, c1));
        float mtot = __shfl_sync(0xffffffffu, mm, 31);
        float d0 = __expf(mtot - cc0), d1 = __expf(mtot - c1);
        sds[2 * tid] = d0; sds[2 * tid + 1] = d1;
        float nd = d0 + d1;
#pragma unroll
        for (int o = 16; o; o >>= 1) nd += __shfl_xor_sync(0xffffffffu, nd, o);
        float ctot = __shfl_sync(0xffffffffu, c1, 31);
        if (tid == 0) { g_Atot[bh * NCH + c] = ctot; g_ndec[bh * NCH + c] = nd; }
    }
    __syncthreads();

    int tj = (tid & 15) * 4;
    int ti = (tid >> 4) * 4;

    {
        float r[4][4];
#pragma unroll
        for (int a = 0; a < 4; a++)
#pragma unroll
            for (int b2 = 0; b2 < 4; b2++) r[a][b2] = 0.f;
        for (int n = 0; n < 64; n++) {
            float cv[4], bv[4];
#pragma unroll
            for (int a = 0; a < 4; a++) cv[a] = sC[ti + a][n];
#pragma unroll
            for (int b2 = 0; b2 < 4; b2++) bv[b2] = sB[tj + b2][n];
#pragma unroll
            for (int a = 0; a < 4; a++)
#pragma unroll
                for (int b2 = 0; b2 < 4; b2++) r[a][b2] = fmaf(cv[a], bv[b2], r[a][b2]);
        }
#pragma unroll
        for (int a = 0; a < 4; a++)
#pragma unroll
            for (int b2 = 0; b2 < 4; b2++) {
                int i = ti + a, j = tj + b2;
                sGL[i][j] = (j <= i) ? r[a][b2] * __expf(smn[i] - scum[j]) : 0.f;
            }
    }
    if (tid < 64) {
        float s = 0.f;
        float m = smn[tid];
        for (int j = 0; j <= tid; j++) s += __expf(m - scum[j]);
        g_ndiag[abase + tid] = s;
    }
    __syncthreads();

    {
        float r[4][4];
#pragma unroll
        for (int a = 0; a < 4; a++)
#pragma unroll
            for (int b2 = 0; b2 < 4; b2++) r[a][b2] = 0.f;
        for (int j = 0; j < 64; j++) {
            float gl[4], xv[4];
#pragma unroll
            for (int a = 0; a < 4; a++) gl[a] = sGL[ti + a][j];
#pragma unroll
            for (int b2 = 0; b2 < 4; b2++) xv[b2] = sX[j][tj + b2];
#pragma unroll
            for (int a = 0; a < 4; a++)
#pragma unroll
                for (int b2 = 0; b2 < 4; b2++) r[a][b2] = fmaf(gl[a], xv[b2], r[a][b2]);
        }
#pragma unroll
        for (int a = 0; a < 4; a++)
            *(float4*)(g_Ydiag + base + (size_t)(ti + a) * 64 + tj)
                = make_float4(r[a][0], r[a][1], r[a][2], r[a][3]);
    }
    {
        float r[4][4];
#pragma unroll
        for (int a = 0; a < 4; a++)
#pragma unroll
            for (int b2 = 0; b2 < 4; b2++) r[a][b2] = 0.f;
        for (int l = 0; l < 64; l++) {
            float d = sds[l];
            float xv[4], bv[4];
#pragma unroll
            for (int a = 0; a < 4; a++) xv[a] = sX[l][ti + a] * d;
#pragma unroll
            for (int b2 = 0; b2 < 4; b2++) bv[b2] = sB[l][tj + b2];
#pragma unroll
            for (int a = 0; a < 4; a++)
#pragma unroll
                for (int b2 = 0; b2 < 4; b2++) r[a][b2] = fmaf(xv[a], bv[b2], r[a][b2]);
        }
        size_t sb = ((size_t)bh * NCH + c) * 4096;
#pragma unroll
        for (int a = 0; a < 4; a++)
            *(float4*)(g_states + sb + (size_t)(ti + a) * 64 + tj)
                = make_float4(r[a][0], r[a][1], r[a][2], r[a][3]);
    }
}

// --------------- chunk recurrence scan --------------------------------------------
__global__ void scan_k()
{
    int bh   = blockIdx.x >> 3;
    int part = blockIdx.x & 7;
    int tid  = threadIdx.x;
    int e0   = part * 512 + tid;
    size_t sb = (size_t)bh * NCH * 4096;

    float r0 = 0.f, r1 = 0.f;
    float minc = 0.f, cc = 0.f, nacc = 0.f;
    g_nstates[sb + e0] = 0.f;
    g_nstates[sb + e0 + 256] = 0.f;
    if (part == 0 && tid == 0) g_nnew[bh * NCH] = 0.f;
    for (int z = 0; z < 63; z++) {
        cc += g_Atot[bh * NCH + z];
        float m2 = fminf(minc, cc);
        float f = __expf(m2 - minc);
        float g = __expf(m2 - cc);
        r0 = r0 * f + g * g_states[sb + (size_t)z * 4096 + e0];
        r1 = r1 * f + g * g_states[sb + (size_t)z * 4096 + e0 + 256];
        minc = m2;
        g_nstates[sb + (size_t)(z + 1) * 4096 + e0] = r0;
        g_nstates[sb + (size_t)(z + 1) * 4096 + e0 + 256] = r1;
        if (part == 0 && tid == 0) {
            nacc = nacc * f + g * g_ndec[bh * NCH + z];
            g_nnew[bh * NCH + z + 1] = nacc;
        }
    }
}

// --------------- Y_off + combine + normalize + bf16 split -------------------------
__global__ __launch_bounds__(256) void yoff_k()
{
    __shared__ float sC[64][65];
    __shared__ float sS[64][65];
    __shared__ float scum[64];
    __shared__ float sdo[64];

    int bh = blockIdx.x >> 6;
    int c  = blockIdx.x & 63;
    int b  = bh >> 4;
    int h  = bh & 15;
    int tid = threadIdx.x;
    size_t baseC = ((size_t)bh * SEQL + (size_t)c * 64) * HD;
    size_t baseS = ((size_t)bh * NCH + c) * 4096;

    {
        const float4* pC = (const float4*)(g_Cm + baseC);
        const float4* pS = (const float4*)(g_nstates + baseS);
        for (int i4 = tid; i4 < 1024; i4 += 256) {
            int l = i4 >> 4, n = (i4 & 15) * 4;
            float4 v = pC[i4]; sC[l][n] = v.x; sC[l][n+1] = v.y; sC[l][n+2] = v.z; sC[l][n+3] = v.w;
            v = pS[i4]; sS[l][n] = v.x; sS[l][n+1] = v.y; sS[l][n+2] = v.z; sS[l][n+3] = v.w;
        }
    }
    if (tid < 32) {
        float a0 = g_cumA[(size_t)bh * SEQL + c * 64 + 2 * tid];
        float a1 = g_cumA[(size_t)bh * SEQL + c * 64 + 2 * tid + 1];
        scum[2 * tid] = a0; scum[2 * tid + 1] = a1;
        float mx = fmaxf(a0, a1);
#pragma unroll
        for (int o = 16; o; o >>= 1) mx = fmaxf(mx, __shfl_xor_sync(0xffffffffu, mx, o));
        sdo[2 * tid]     = __expf(a0 - mx);
        sdo[2 * tid + 1] = __expf(a1 - mx);
    }
    __syncthreads();

    float nn = g_nnew[bh * NCH + c];
    int tl = (tid >> 4) * 4;
    int tp = (tid & 15) * 4;
    float r[4][4];
#pragma unroll
    for (int a = 0; a < 4; a++)
#pragma unroll
        for (int b2 = 0; b2 < 4; b2++) r[a][b2] = 0.f;
    for (int n = 0; n < 64; n++) {
        float cv[4], sv[4];
#pragma unroll
        for (int a = 0; a < 4; a++) cv[a] = sC[tl + a][n];
#pragma unroll
        for (int b2 = 0; b2 < 4; b2++) sv[b2] = sS[tp + b2][n];
#pragma unroll
        for (int a = 0; a < 4; a++)
#pragma unroll
            for (int b2 = 0; b2 < 4; b2++) r[a][b2] = fmaf(cv[a], sv[b2], r[a][b2]);
    }
#pragma unroll
    for (int a = 0; a < 4; a++) {
        int l = tl + a;
        float d = sdo[l];
        float nm = g_ndiag[(size_t)bh * SEQL + c * 64 + l] + nn * d;
        float inv = 1.f / nm;
        int s = c * 64 + l;
        size_t rowb = ((size_t)b * SEQL + s) * K3 + h * 64;
        const float4 yv = *(const float4*)(g_Ydiag + baseC + (size_t)l * 64 + tp);
        float v0 = (yv.x + d * r[a][0]) * inv;
        float v1 = (yv.y + d * r[a][1]) * inv;
        float v2 = (yv.z + d * r[a][2]) * inv;
        float v3 = (yv.w + d * r[a][3]) * inv;
        __nv_bfloat16 h0 = __float2bfloat16(v0), h1 = __float2bfloat16(v1);
        __nv_bfloat16 h2 = __float2bfloat16(v2), h3 = __float2bfloat16(v3);
        __nv_bfloat16 l0 = __float2bfloat16(v0 - __bfloat162float(h0));
        __nv_bfloat16 l1 = __float2bfloat16(v1 - __bfloat162float(h1));
        __nv_bfloat16 l2 = __float2bfloat16(v2 - __bfloat162float(h2));
        __nv_bfloat16 l3 = __float2bfloat16(v3 - __bfloat162float(h3));
        __nv_bfloat162 hp0 = __halves2bfloat162(h0, h1), hp1 = __halves2bfloat162(h2, h3);
        __nv_bfloat162 lp0 = __halves2bfloat162(l0, l1), lp1 = __halves2bfloat162(l2, l3);
        uint2 hu, lu;
        hu.x = *(uint32_t*)&hp0; hu.y = *(uint32_t*)&hp1;
        lu.x = *(uint32_t*)&lp0; lu.y = *(uint32_t*)&lp1;
        *(uint2*)(g_ys + rowb + tp)              = hu;
        *(uint2*)(g_ys + rowb + tp + DMODEL)     = hu;
        *(uint2*)(g_ys + rowb + tp + 2 * DMODEL) = lu;
    }
}

// ------------------------------- launch ---------------------------------------------
extern "C" void kernel_launch(void* const* d_in, const int* in_sizes, int n_in,
                              void* d_out, int out_size)
{
    const float* x   = (const float*)d_in[0];
    const float* ipw = (const float*)d_in[1];
    const float* cw  = (const float*)d_in[2];
    const float* cb  = (const float*)d_in[3];
    const float* wb  = (const float*)d_in[4];
    const float* opw = (const float*)d_in[5];
    float* out = (float*)d_out;

    float *p_xw = nullptr;
    __nv_bfloat16 *p_xs, *p_ws, *p_w2s, *p_ys;
    cudaGetSymbolAddress((void**)&p_xw, g_xw);
    cudaGetSymbolAddress((void**)&p_xs, g_xs);
    cudaGetSymbolAddress((void**)&p_ws, g_ws);
    cudaGetSymbolAddress((void**)&p_w2s, g_w2s);
    cudaGetSymbolAddress((void**)&p_ys, g_ys);

    const int SMEM_CHUNK = 4 * 64 * 65 * 4;
    cudaFuncSetAttribute(chunk_k, cudaFuncAttributeMaxDynamicSharedMemorySize, SMEM_CHUNK);
    const int SMEM_GEMM = NSTG * (int)STGB;
    cudaFuncSetAttribute(mma_gemm_k, cudaFuncAttributeMaxDynamicSharedMemorySize, SMEM_GEMM);

    // 0) bf16 splits
    split_k<<<(BSN * DMODEL + 255) / 256, 256>>>(x, p_xs, BSN, DMODEL, BSN, 0);
    split_k<<<(NPAD_IP * DMODEL + 255) / 256, 256>>>(ipw, p_ws, DINP, DMODEL, NPAD_IP, 1);
    split_k<<<(DMODEL * DMODEL + 255) / 256, 256>>>(opw, p_w2s, DMODEL, DMODEL, DMODEL, 1);

    // 1) in_proj via HMMA
    {
        dim3 g(NPAD_IP / 128, BSN / 128);
        mma_gemm_k<<<g, 256, SMEM_GEMM>>>(p_xs, p_ws, p_xw, K3, DINP, DINP);
    }

    // 2) tiled conv + split
    {
        dim3 g(BSN / 32, CONVD / 256);
        conv_split_k<<<g, 256>>>(cw, cb);
    }

    // 3) per-chunk tiles (A-scale fused)
    chunk_k<<<BHN * NCH, 256, SMEM_CHUNK>>>(wb);

    // 4) chunk recurrence scan
    scan_k<<<BHN * 8, 256>>>();

    // 5) off-diagonal + normalize + fused bf16 split
    yoff_k<<<BHN * NCH, 256>>>();

    // 6) out_proj via HMMA
    {
        dim3 g(DMODEL / 128, BSN / 128);
        mma_gemm_k<<<g, 256, SMEM_GEMM>>>(p_ys, p_w2s, out, K3, DMODEL, DMODEL);
    }
}